// round 1
// baseline (speedup 1.0000x reference)
#include <cuda_runtime.h>
#include <cuda_bf16.h>
#include <math.h>

// ---------------- problem constants ----------------
#define BATCH 256
#define SEQ   196
#define EMB   256
#define HEADS 8
#define HDIM  32
#define NBLK  4
#define FF    1024
#define NQBIT 8
#define NCLS  10
#define TOK   (BATCH*SEQ)          // 50176

// ---------------- device scratch (static, no allocation) ----------------
__device__ float g_h[(size_t)TOK * EMB];        //  51.4 MB
__device__ float g_qkv[(size_t)TOK * 3 * EMB];  // 154   MB
__device__ float g_attn[(size_t)TOK * EMB];     //  51.4 MB
__device__ float g_tmp[(size_t)TOK * EMB];      //  51.4 MB
__device__ float g_mid[(size_t)TOK * FF];       // 205   MB
__device__ float g_feat[(size_t)TOK * 4];       //   0.8 MB

// ============================================================
// 1. Quanvolution: depthwise 2x2 stride2 (groups=4) + pointwise 1x1,
//    then channel-major reshape to feat[b, s, c].
//    flat = s*4 + c ; ch = flat/196 ; sp = flat%196 ; (i,j) = (sp/14, sp%14)
// ============================================================
__global__ void quanv_kernel(const float* __restrict__ x,
                             const float* __restrict__ qw,   // [4,1,2,2]
                             const float* __restrict__ qb,   // [4]
                             const float* __restrict__ pw,   // [4,4,1,1]
                             const float* __restrict__ pb,   // [4]
                             float* __restrict__ feat)
{
    int idx = blockIdx.x * 256 + threadIdx.x;           // B*S*4 = 200704
    if (idx >= TOK * 4) return;
    int c  = idx & 3;
    int s  = (idx >> 2) % SEQ;
    int b  = idx / (SEQ * 4);
    int flat = s * 4 + c;
    int ch = flat / SEQ;
    int sp = flat % SEQ;
    int i  = sp / 14, j = sp % 14;

    float acc = pb[ch];
#pragma unroll
    for (int c2 = 0; c2 < 4; c2++) {
        const float* xb = x + (((size_t)b * 4 + c2) * 28 + 2 * i) * 28 + 2 * j;
        float conv = qb[c2]
                   + xb[0]  * qw[c2 * 4 + 0]
                   + xb[1]  * qw[c2 * 4 + 1]
                   + xb[28] * qw[c2 * 4 + 2]
                   + xb[29] * qw[c2 * 4 + 3];
        acc += pw[ch * 4 + c2] * conv;
    }
    feat[idx] = acc;
}

// ============================================================
// 2. Embedding (feat @ embed_w^T + b) + sinusoidal positional encoding
// ============================================================
__global__ void embed_kernel(const float* __restrict__ feat,
                             const float* __restrict__ ew,   // [E,4]
                             const float* __restrict__ eb,   // [E]
                             float* __restrict__ h)
{
    int m = blockIdx.x;          // token
    int e = threadIdx.x;         // 0..255
    float4 f = *(const float4*)(feat + (size_t)m * 4);
    float4 w = *(const float4*)(ew + (size_t)e * 4);
    float acc = eb[e] + f.x * w.x + f.y * w.y + f.z * w.z + f.w * w.w;
    int s = m % SEQ;
    int p2 = e & ~1;             // 2*(e/2)
    float ang = (float)s * expf((float)p2 * (-9.210340371976184f / 256.0f));
    acc += (e & 1) ? cosf(ang) : sinf(ang);
    h[(size_t)m * EMB + e] = acc;
}

// ============================================================
// 3. Tiled SGEMM (NT):  C[m,n] = sum_k A[m,k] * W[n,k] + bias[n] (+ resid)
//    128x128 tile, BK=8, 256 threads, 8x8 per thread.
//    Requires M%128==0, N%128==0, K%8==0 (true for all shapes here).
// ============================================================
template<bool RESID>
__global__ void __launch_bounds__(256)
sgemm_nt(const float* __restrict__ A, const float* __restrict__ W,
         const float* __restrict__ bias, const float* __restrict__ resid,
         float* __restrict__ C, int M, int N, int K)
{
    __shared__ float As[8][132];
    __shared__ float Ws[8][132];
    const int bm = blockIdx.y * 128;
    const int bn = blockIdx.x * 128;
    const int tid = threadIdx.x;
    const int lrow = tid >> 1;           // 0..127
    const int lk   = (tid & 1) << 2;     // 0 or 4
    const int tx = tid & 15;             // n dim
    const int ty = tid >> 4;             // m dim

    float acc[8][8];
#pragma unroll
    for (int i = 0; i < 8; i++)
#pragma unroll
        for (int j = 0; j < 8; j++) acc[i][j] = 0.f;

    const float* Ap = A + (size_t)(bm + lrow) * K + lk;
    const float* Wp = W + (size_t)(bn + lrow) * K + lk;

    for (int k0 = 0; k0 < K; k0 += 8) {
        float4 av = *(const float4*)(Ap + k0);
        float4 wv = *(const float4*)(Wp + k0);
        As[lk + 0][lrow] = av.x; As[lk + 1][lrow] = av.y;
        As[lk + 2][lrow] = av.z; As[lk + 3][lrow] = av.w;
        Ws[lk + 0][lrow] = wv.x; Ws[lk + 1][lrow] = wv.y;
        Ws[lk + 2][lrow] = wv.z; Ws[lk + 3][lrow] = wv.w;
        __syncthreads();
#pragma unroll
        for (int kk = 0; kk < 8; kk++) {
            float ra[8], rb[8];
#pragma unroll
            for (int i = 0; i < 8; i++) ra[i] = As[kk][ty * 8 + i];
#pragma unroll
            for (int j = 0; j < 8; j++) rb[j] = Ws[kk][tx * 8 + j];
#pragma unroll
            for (int i = 0; i < 8; i++)
#pragma unroll
                for (int j = 0; j < 8; j++) acc[i][j] += ra[i] * rb[j];
        }
        __syncthreads();
    }

#pragma unroll
    for (int i = 0; i < 8; i++) {
        int m = bm + ty * 8 + i;
#pragma unroll
        for (int j = 0; j < 8; j++) {
            int n = bn + tx * 8 + j;
            float v = acc[i][j] + bias[n];
            if (RESID) v += resid[(size_t)m * N + n];
            C[(size_t)m * N + n] = v;
        }
    }
}

// ============================================================
// 4. Attention per (head, batch):  K,V staged in dynamic smem (49KB),
//    2-pass softmax (max pass, then exp+accumulate), 1 query per thread.
// ============================================================
__global__ void __launch_bounds__(256)
attention_kernel(const float* __restrict__ qkv, float* __restrict__ o)
{
    extern __shared__ float sm[];
    float* Ks = sm;                 // [196][32]
    float* Vs = sm + SEQ * HDIM;
    const int hh = blockIdx.x;
    const int b  = blockIdx.y;
    const int tid = threadIdx.x;
    const float* base = qkv + (size_t)b * SEQ * (3 * EMB);

    for (int i = tid; i < SEQ * 8; i += 256) {
        int s = i >> 3, d4 = (i & 7) << 2;
        const float* row = base + (size_t)s * (3 * EMB) + hh * HDIM + d4;
        *(float4*)(Ks + s * HDIM + d4) = *(const float4*)(row + EMB);
        *(float4*)(Vs + s * HDIM + d4) = *(const float4*)(row + 2 * EMB);
    }
    __syncthreads();

    if (tid < SEQ) {
        const float scale = 0.17677669529663687f;   // 1/sqrt(32)
        float qv[HDIM];
        const float* qp = base + (size_t)tid * (3 * EMB) + hh * HDIM;
#pragma unroll
        for (int d4 = 0; d4 < 8; d4++) {
            float4 t = *(const float4*)(qp + d4 * 4);
            qv[d4 * 4 + 0] = t.x * scale; qv[d4 * 4 + 1] = t.y * scale;
            qv[d4 * 4 + 2] = t.z * scale; qv[d4 * 4 + 3] = t.w * scale;
        }
        // pass 1: row max
        float mmax = -1e30f;
        for (int t = 0; t < SEQ; t++) {
            const float4* kr = (const float4*)(Ks + t * HDIM);
            float s = 0.f;
#pragma unroll
            for (int d4 = 0; d4 < 8; d4++) {
                float4 k4 = kr[d4];
                s += qv[d4*4+0]*k4.x + qv[d4*4+1]*k4.y + qv[d4*4+2]*k4.z + qv[d4*4+3]*k4.w;
            }
            mmax = fmaxf(mmax, s);
        }
        // pass 2: exp + accumulate
        float acc[HDIM];
#pragma unroll
        for (int d = 0; d < HDIM; d++) acc[d] = 0.f;
        float l = 0.f;
        for (int t = 0; t < SEQ; t++) {
            const float4* kr = (const float4*)(Ks + t * HDIM);
            float s = 0.f;
#pragma unroll
            for (int d4 = 0; d4 < 8; d4++) {
                float4 k4 = kr[d4];
                s += qv[d4*4+0]*k4.x + qv[d4*4+1]*k4.y + qv[d4*4+2]*k4.z + qv[d4*4+3]*k4.w;
            }
            float p = __expf(s - mmax);
            l += p;
            const float4* vr = (const float4*)(Vs + t * HDIM);
#pragma unroll
            for (int d4 = 0; d4 < 8; d4++) {
                float4 v4 = vr[d4];
                acc[d4*4+0] += p * v4.x; acc[d4*4+1] += p * v4.y;
                acc[d4*4+2] += p * v4.z; acc[d4*4+3] += p * v4.w;
            }
        }
        float inv = 1.f / l;
        float* op = o + (size_t)(b * SEQ + tid) * EMB + hh * HDIM;
#pragma unroll
        for (int d4 = 0; d4 < 8; d4++) {
            float4 r;
            r.x = acc[d4*4+0] * inv; r.y = acc[d4*4+1] * inv;
            r.z = acc[d4*4+2] * inv; r.w = acc[d4*4+3] * inv;
            *(float4*)(op + d4 * 4) = r;
        }
    }
}

// ============================================================
// 5. LayerNorm over last dim (E=256): one warp per row.
// ============================================================
__global__ void __launch_bounds__(256)
ln_kernel(const float* __restrict__ x, const float* __restrict__ g,
          const float* __restrict__ b, float* __restrict__ y)
{
    int row  = blockIdx.x * 8 + (threadIdx.x >> 5);
    int lane = threadIdx.x & 31;
    const float* xr = x + (size_t)row * EMB;
    float v[8];
    float s = 0.f;
#pragma unroll
    for (int i = 0; i < 8; i++) { v[i] = xr[i * 32 + lane]; s += v[i]; }
#pragma unroll
    for (int o = 16; o > 0; o >>= 1) s += __shfl_xor_sync(0xffffffffu, s, o);
    float mean = s * (1.f / 256.f);
    float q = 0.f;
#pragma unroll
    for (int i = 0; i < 8; i++) { float d = v[i] - mean; q += d * d; }
#pragma unroll
    for (int o = 16; o > 0; o >>= 1) q += __shfl_xor_sync(0xffffffffu, q, o);
    float rstd = rsqrtf(q * (1.f / 256.f) + 1e-5f);
    float* yr = y + (size_t)row * EMB;
#pragma unroll
    for (int i = 0; i < 8; i++) {
        int c = i * 32 + lane;
        yr[c] = (v[i] - mean) * rstd * g[c] + b[c];
    }
}

// ============================================================
// 6. Quantum FFN mid: qm = cos(h[:, :8]) * cos(theta); mid = relu(qm @ l1^T + b)
//    32 token rows per block, l1_w (8192 floats) staged in padded smem.
// ============================================================
__global__ void __launch_bounds__(256)
ffn_mid_kernel(const float* __restrict__ h, const float* __restrict__ l1w,
               const float* __restrict__ l1b, const float* __restrict__ theta,
               float* __restrict__ mid)
{
    __shared__ float sw[FF][9];      // padded: stride 9 kills bank conflicts
    __shared__ float sb[FF];
    __shared__ float scq[32][8];
    const int tid = threadIdx.x;
    const int m0 = blockIdx.x * 32;

    for (int i = tid; i < FF * 8; i += 256) sw[i >> 3][i & 7] = l1w[i];
    for (int i = tid; i < FF;     i += 256) sb[i] = l1b[i];
    {
        int r = tid >> 3, q = tid & 7;
        float hv = h[(size_t)(m0 + r) * EMB + q];
        scq[r][q] = cosf(hv) * cosf(theta[q]);
    }
    __syncthreads();

    for (int r = 0; r < 32; r++) {
        float c[8];
#pragma unroll
        for (int q = 0; q < 8; q++) c[q] = scq[r][q];
        float* mp = mid + (size_t)(m0 + r) * FF;
        for (int n = tid; n < FF; n += 256) {
            float acc = sb[n];
#pragma unroll
            for (int q = 0; q < 8; q++) acc += c[q] * sw[n][q];
            mp[n] = fmaxf(acc, 0.f);
        }
    }
}

// ============================================================
// 7. Mean-pool over sequence + classifier (E=256 -> 10)
// ============================================================
__global__ void __launch_bounds__(256)
pool_cls_kernel(const float* __restrict__ h, const float* __restrict__ cw,
                const float* __restrict__ cb, float* __restrict__ out)
{
    int b = blockIdx.x;
    int e = threadIdx.x;
    const float* hp = h + (size_t)b * SEQ * EMB + e;
    float s = 0.f;
    for (int t = 0; t < SEQ; t++) s += hp[(size_t)t * EMB];
    __shared__ float sp[EMB];
    sp[e] = s * (1.f / 196.f);
    __syncthreads();
    if (e < NCLS) {
        float acc = cb[e];
        const float* w = cw + e * EMB;
        for (int k = 0; k < EMB; k++) acc += sp[k] * w[k];
        out[b * NCLS + e] = acc;
    }
}

// ============================================================
// launcher
// ============================================================
extern "C" void kernel_launch(void* const* d_in, const int* in_sizes, int n_in,
                              void* d_out, int out_size)
{
    const float* x    = (const float*)d_in[0];
    const float* qfw  = (const float*)d_in[1];
    const float* qfb  = (const float*)d_in[2];
    const float* pww  = (const float*)d_in[3];
    const float* pwb  = (const float*)d_in[4];
    const float* embw = (const float*)d_in[5];
    const float* embb = (const float*)d_in[6];
    const float* inw  = (const float*)d_in[7];
    const float* inb  = (const float*)d_in[8];
    const float* outw = (const float*)d_in[9];
    const float* outb = (const float*)d_in[10];
    const float* thet = (const float*)d_in[11];
    const float* l1w  = (const float*)d_in[12];
    const float* l1b  = (const float*)d_in[13];
    const float* l2w  = (const float*)d_in[14];
    const float* l2b  = (const float*)d_in[15];
    const float* ln1g = (const float*)d_in[16];
    const float* ln1b = (const float*)d_in[17];
    const float* ln2g = (const float*)d_in[18];
    const float* ln2b = (const float*)d_in[19];
    const float* clsw = (const float*)d_in[20];
    const float* clsb = (const float*)d_in[21];
    float* out = (float*)d_out;

    float *h, *qkv, *attn, *tmp, *mid, *feat;
    cudaGetSymbolAddress((void**)&h,    g_h);
    cudaGetSymbolAddress((void**)&qkv,  g_qkv);
    cudaGetSymbolAddress((void**)&attn, g_attn);
    cudaGetSymbolAddress((void**)&tmp,  g_tmp);
    cudaGetSymbolAddress((void**)&mid,  g_mid);
    cudaGetSymbolAddress((void**)&feat, g_feat);

    const int SMEM_ATTN = SEQ * HDIM * 4 * 2;   // 50176 bytes
    cudaFuncSetAttribute(attention_kernel,
                         cudaFuncAttributeMaxDynamicSharedMemorySize, SMEM_ATTN);

    quanv_kernel<<<(TOK * 4 + 255) / 256, 256>>>(x, qfw, qfb, pww, pwb, feat);
    embed_kernel<<<TOK, 256>>>(feat, embw, embb, h);

    for (int i = 0; i < NBLK; i++) {
        // QKV projection: [TOK,256] x [768,256]^T
        sgemm_nt<false><<<dim3(3 * EMB / 128, TOK / 128), 256>>>(
            h, inw + (size_t)i * 3 * EMB * EMB, inb + (size_t)i * 3 * EMB,
            nullptr, qkv, TOK, 3 * EMB, EMB);

        attention_kernel<<<dim3(HEADS, BATCH), 256, SMEM_ATTN>>>(qkv, attn);

        // out-proj + residual
        sgemm_nt<true><<<dim3(EMB / 128, TOK / 128), 256>>>(
            attn, outw + (size_t)i * EMB * EMB, outb + (size_t)i * EMB,
            h, tmp, TOK, EMB, EMB);
        ln_kernel<<<TOK / 8, 256>>>(tmp, ln1g + (size_t)i * EMB, ln1b + (size_t)i * EMB, h);

        // quantum FFN
        ffn_mid_kernel<<<TOK / 32, 256>>>(h, l1w + (size_t)i * FF * NQBIT,
                                          l1b + (size_t)i * FF, thet + (size_t)i * NQBIT, mid);
        sgemm_nt<true><<<dim3(EMB / 128, TOK / 128), 256>>>(
            mid, l2w + (size_t)i * EMB * FF, l2b + (size_t)i * EMB,
            h, tmp, TOK, EMB, FF);
        ln_kernel<<<TOK / 8, 256>>>(tmp, ln2g + (size_t)i * EMB, ln2b + (size_t)i * EMB, h);
    }

    pool_cls_kernel<<<BATCH, 256>>>(h, clsw, clsb, out);
}

// round 2
// speedup vs baseline: 1.7534x; 1.7534x over previous
#include <cuda_runtime.h>
#include <cuda_bf16.h>
#include <math.h>

// ---------------- problem constants ----------------
#define BATCH 256
#define SEQ   196
#define EMB   256
#define HEADS 8
#define HDIM  32
#define NBLK  4
#define FF    1024
#define NQBIT 8
#define NCLS  10
#define TOK   (BATCH*SEQ)          // 50176

// ---------------- device scratch (static, no allocation) ----------------
__device__ float g_h[(size_t)TOK * EMB];
__device__ float g_qkv[(size_t)TOK * 3 * EMB];
__device__ float g_attn[(size_t)TOK * EMB];
__device__ float g_tmp[(size_t)TOK * EMB];
__device__ float g_mid[(size_t)TOK * FF];
__device__ float g_feat[(size_t)TOK * 4];
// tf32-rounded weight copies
__device__ float g_w_in[(size_t)NBLK * 3 * EMB * EMB];   // 786432
__device__ float g_w_out[(size_t)NBLK * EMB * EMB];      // 262144
__device__ float g_w_l2[(size_t)NBLK * EMB * FF];        // 1048576

// ---------------- helpers ----------------
__device__ __forceinline__ float rtf32(float x) {
    unsigned u;
    asm("cvt.rna.tf32.f32 %0, %1;" : "=r"(u) : "f"(x));
    return __uint_as_float(u);
}
__device__ __forceinline__ void cp_async16(void* smem, const void* gmem) {
    unsigned s = (unsigned)__cvta_generic_to_shared(smem);
    asm volatile("cp.async.ca.shared.global [%0], [%1], 16;" :: "r"(s), "l"(gmem));
}
__device__ __forceinline__ void cp_commit() { asm volatile("cp.async.commit_group;"); }
template<int N> __device__ __forceinline__ void cp_wait() {
    asm volatile("cp.async.wait_group %0;" :: "n"(N));
}

// ============================================================
// 0. weight tf32 rounding pre-pass
// ============================================================
__global__ void tf32_cvt_kernel(const float* __restrict__ src, float* __restrict__ dst, int n)
{
    int i = blockIdx.x * 256 + threadIdx.x;
    if (i < n) dst[i] = rtf32(src[i]);
}

// ============================================================
// 1. Quanvolution
// ============================================================
__global__ void quanv_kernel(const float* __restrict__ x,
                             const float* __restrict__ qw,
                             const float* __restrict__ qb,
                             const float* __restrict__ pw,
                             const float* __restrict__ pb,
                             float* __restrict__ feat)
{
    int idx = blockIdx.x * 256 + threadIdx.x;
    if (idx >= TOK * 4) return;
    int c  = idx & 3;
    int s  = (idx >> 2) % SEQ;
    int b  = idx / (SEQ * 4);
    int flat = s * 4 + c;
    int ch = flat / SEQ;
    int sp = flat % SEQ;
    int i  = sp / 14, j = sp % 14;

    float acc = pb[ch];
#pragma unroll
    for (int c2 = 0; c2 < 4; c2++) {
        const float* xb = x + (((size_t)b * 4 + c2) * 28 + 2 * i) * 28 + 2 * j;
        float conv = qb[c2]
                   + xb[0]  * qw[c2 * 4 + 0]
                   + xb[1]  * qw[c2 * 4 + 1]
                   + xb[28] * qw[c2 * 4 + 2]
                   + xb[29] * qw[c2 * 4 + 3];
        acc += pw[ch * 4 + c2] * conv;
    }
    feat[idx] = acc;
}

// ============================================================
// 2. Embedding + positional encoding (output tf32-rounded: feeds mma GEMM)
// ============================================================
__global__ void embed_kernel(const float* __restrict__ feat,
                             const float* __restrict__ ew,
                             const float* __restrict__ eb,
                             float* __restrict__ h)
{
    int m = blockIdx.x;
    int e = threadIdx.x;
    float4 f = *(const float4*)(feat + (size_t)m * 4);
    float4 w = *(const float4*)(ew + (size_t)e * 4);
    float acc = eb[e] + f.x * w.x + f.y * w.y + f.z * w.z + f.w * w.w;
    int s = m % SEQ;
    int p2 = e & ~1;
    float ang = (float)s * expf((float)p2 * (-9.210340371976184f / 256.0f));
    acc += (e & 1) ? cosf(ang) : sinf(ang);
    h[(size_t)m * EMB + e] = rtf32(acc);
}

// ============================================================
// 3. tf32 tensor-core GEMM (NT): C = A[M,K] * W[N,K]^T + bias (+ resid)
//    CTA 128x128, K-chunk 32, 8 warps (2x4) with 64x32 warp tiles.
//    cp.async double-buffered smem; padded stride 36 -> conflict-free frags.
//    Operands must be pre-rounded to tf32 (rna) in global memory.
// ============================================================
#define GK 36          // padded row stride (floats)
#define GBUF (128*GK)  // one buffer of one matrix

template<bool RESID>
__global__ void __launch_bounds__(256, 2)
mma_gemm(const float* __restrict__ A, const float* __restrict__ W,
         const float* __restrict__ bias, const float* __restrict__ resid,
         float* __restrict__ C, int M, int N, int K)
{
    extern __shared__ float sm[];
    float* sA = sm;               // [2][128][36]
    float* sW = sm + 2 * GBUF;    // [2][128][36]

    const int tid  = threadIdx.x;
    const int bm   = blockIdx.y * 128;
    const int bn   = blockIdx.x * 128;
    const int lane = tid & 31;
    const int wid  = tid >> 5;
    const int wm   = (wid & 1) * 64;
    const int wn   = (wid >> 1) * 32;
    const int ln4  = lane >> 2;
    const int lnm  = lane & 3;

    // staging assignment: thread -> row r, 16-float half kb
    const int r  = tid >> 1;
    const int kb = (tid & 1) * 16;
    const float* Ag = A + (size_t)(bm + r) * K + kb;
    const float* Wg = W + (size_t)(bn + r) * K + kb;

    float acc[4][4][4];
#pragma unroll
    for (int i = 0; i < 4; i++)
#pragma unroll
        for (int j = 0; j < 4; j++)
#pragma unroll
            for (int t = 0; t < 4; t++) acc[i][j][t] = 0.f;

    const int nc = K >> 5;

    // prologue: chunk 0 -> buffer 0
    {
        float* aw = sA + r * GK + kb;
        float* ww = sW + r * GK + kb;
#pragma unroll
        for (int q = 0; q < 4; q++) {
            cp_async16(aw + q * 4, Ag + q * 4);
            cp_async16(ww + q * 4, Wg + q * 4);
        }
        cp_commit();
    }

    for (int c = 0; c < nc; c++) {
        const int buf = c & 1;
        if (c + 1 < nc) {
            const int nb = buf ^ 1;
            const float* Ag2 = Ag + (c + 1) * 32;
            const float* Wg2 = Wg + (c + 1) * 32;
            float* aw = sA + nb * GBUF + r * GK + kb;
            float* ww = sW + nb * GBUF + r * GK + kb;
#pragma unroll
            for (int q = 0; q < 4; q++) {
                cp_async16(aw + q * 4, Ag2 + q * 4);
                cp_async16(ww + q * 4, Wg2 + q * 4);
            }
            cp_commit();
            cp_wait<1>();
        } else {
            cp_wait<0>();
        }
        __syncthreads();

        const float* cA = sA + buf * GBUF;
        const float* cW = sW + buf * GBUF;

#pragma unroll
        for (int s = 0; s < 4; s++) {
            const int k0 = s * 8;
            unsigned af[4][4], bf[4][2];
#pragma unroll
            for (int i = 0; i < 4; i++) {
                const float* p = cA + (wm + i * 16 + ln4) * GK + k0 + lnm;
                af[i][0] = __float_as_uint(p[0]);
                af[i][1] = __float_as_uint(p[8 * GK]);
                af[i][2] = __float_as_uint(p[4]);
                af[i][3] = __float_as_uint(p[8 * GK + 4]);
            }
#pragma unroll
            for (int j = 0; j < 4; j++) {
                const float* p = cW + (wn + j * 8 + ln4) * GK + k0 + lnm;
                bf[j][0] = __float_as_uint(p[0]);
                bf[j][1] = __float_as_uint(p[4]);
            }
#pragma unroll
            for (int i = 0; i < 4; i++)
#pragma unroll
                for (int j = 0; j < 4; j++) {
                    asm volatile(
                        "mma.sync.aligned.m16n8k8.row.col.f32.tf32.tf32.f32 "
                        "{%0,%1,%2,%3}, {%4,%5,%6,%7}, {%8,%9}, {%0,%1,%2,%3};"
                        : "+f"(acc[i][j][0]), "+f"(acc[i][j][1]),
                          "+f"(acc[i][j][2]), "+f"(acc[i][j][3])
                        : "r"(af[i][0]), "r"(af[i][1]), "r"(af[i][2]), "r"(af[i][3]),
                          "r"(bf[j][0]), "r"(bf[j][1]));
                }
        }
        __syncthreads();
    }

    // epilogue
#pragma unroll
    for (int i = 0; i < 4; i++) {
        const int row0 = bm + wm + i * 16 + ln4;
#pragma unroll
        for (int j = 0; j < 4; j++) {
            const int col = bn + wn + j * 8 + 2 * lnm;
            const float b0 = bias[col], b1 = bias[col + 1];
            float2 v0 = make_float2(acc[i][j][0] + b0, acc[i][j][1] + b1);
            float2 v1 = make_float2(acc[i][j][2] + b0, acc[i][j][3] + b1);
            if (RESID) {
                float2 r0 = *(const float2*)(resid + (size_t)row0 * N + col);
                float2 r1 = *(const float2*)(resid + (size_t)(row0 + 8) * N + col);
                v0.x += r0.x; v0.y += r0.y;
                v1.x += r1.x; v1.y += r1.y;
            }
            *(float2*)(C + (size_t)row0 * N + col)       = v0;
            *(float2*)(C + (size_t)(row0 + 8) * N + col) = v1;
        }
    }
}

// ============================================================
// 4. Attention per (head, batch) — output tf32-rounded (feeds mma GEMM)
// ============================================================
__global__ void __launch_bounds__(256)
attention_kernel(const float* __restrict__ qkv, float* __restrict__ o)
{
    extern __shared__ float smA[];
    float* Ks = smA;
    float* Vs = smA + SEQ * HDIM;
    const int hh = blockIdx.x;
    const int b  = blockIdx.y;
    const int tid = threadIdx.x;
    const float* base = qkv + (size_t)b * SEQ * (3 * EMB);

    for (int i = tid; i < SEQ * 8; i += 256) {
        int s = i >> 3, d4 = (i & 7) << 2;
        const float* row = base + (size_t)s * (3 * EMB) + hh * HDIM + d4;
        *(float4*)(Ks + s * HDIM + d4) = *(const float4*)(row + EMB);
        *(float4*)(Vs + s * HDIM + d4) = *(const float4*)(row + 2 * EMB);
    }
    __syncthreads();

    if (tid < SEQ) {
        const float scale = 0.17677669529663687f;
        float qv[HDIM];
        const float* qp = base + (size_t)tid * (3 * EMB) + hh * HDIM;
#pragma unroll
        for (int d4 = 0; d4 < 8; d4++) {
            float4 t = *(const float4*)(qp + d4 * 4);
            qv[d4 * 4 + 0] = t.x * scale; qv[d4 * 4 + 1] = t.y * scale;
            qv[d4 * 4 + 2] = t.z * scale; qv[d4 * 4 + 3] = t.w * scale;
        }
        float mmax = -1e30f;
        for (int t = 0; t < SEQ; t++) {
            const float4* kr = (const float4*)(Ks + t * HDIM);
            float s = 0.f;
#pragma unroll
            for (int d4 = 0; d4 < 8; d4++) {
                float4 k4 = kr[d4];
                s += qv[d4*4+0]*k4.x + qv[d4*4+1]*k4.y + qv[d4*4+2]*k4.z + qv[d4*4+3]*k4.w;
            }
            mmax = fmaxf(mmax, s);
        }
        float acc[HDIM];
#pragma unroll
        for (int d = 0; d < HDIM; d++) acc[d] = 0.f;
        float l = 0.f;
        for (int t = 0; t < SEQ; t++) {
            const float4* kr = (const float4*)(Ks + t * HDIM);
            float s = 0.f;
#pragma unroll
            for (int d4 = 0; d4 < 8; d4++) {
                float4 k4 = kr[d4];
                s += qv[d4*4+0]*k4.x + qv[d4*4+1]*k4.y + qv[d4*4+2]*k4.z + qv[d4*4+3]*k4.w;
            }
            float p = __expf(s - mmax);
            l += p;
            const float4* vr = (const float4*)(Vs + t * HDIM);
#pragma unroll
            for (int d4 = 0; d4 < 8; d4++) {
                float4 v4 = vr[d4];
                acc[d4*4+0] += p * v4.x; acc[d4*4+1] += p * v4.y;
                acc[d4*4+2] += p * v4.z; acc[d4*4+3] += p * v4.w;
            }
        }
        float inv = 1.f / l;
        float* op = o + (size_t)(b * SEQ + tid) * EMB + hh * HDIM;
#pragma unroll
        for (int d4 = 0; d4 < 8; d4++) {
            float4 rr;
            rr.x = rtf32(acc[d4*4+0] * inv); rr.y = rtf32(acc[d4*4+1] * inv);
            rr.z = rtf32(acc[d4*4+2] * inv); rr.w = rtf32(acc[d4*4+3] * inv);
            *(float4*)(op + d4 * 4) = rr;
        }
    }
}

// ============================================================
// 5. LayerNorm — output tf32-rounded (feeds mma GEMM as A and resid)
// ============================================================
__global__ void __launch_bounds__(256)
ln_kernel(const float* __restrict__ x, const float* __restrict__ g,
          const float* __restrict__ b, float* __restrict__ y)
{
    int row  = blockIdx.x * 8 + (threadIdx.x >> 5);
    int lane = threadIdx.x & 31;
    const float* xr = x + (size_t)row * EMB;
    float v[8];
    float s = 0.f;
#pragma unroll
    for (int i = 0; i < 8; i++) { v[i] = xr[i * 32 + lane]; s += v[i]; }
#pragma unroll
    for (int o = 16; o > 0; o >>= 1) s += __shfl_xor_sync(0xffffffffu, s, o);
    float mean = s * (1.f / 256.f);
    float q = 0.f;
#pragma unroll
    for (int i = 0; i < 8; i++) { float d = v[i] - mean; q += d * d; }
#pragma unroll
    for (int o = 16; o > 0; o >>= 1) q += __shfl_xor_sync(0xffffffffu, q, o);
    float rstd = rsqrtf(q * (1.f / 256.f) + 1e-5f);
    float* yr = y + (size_t)row * EMB;
#pragma unroll
    for (int i = 0; i < 8; i++) {
        int c = i * 32 + lane;
        yr[c] = rtf32((v[i] - mean) * rstd * g[c] + b[c]);
    }
}

// ============================================================
// 6. Quantum FFN mid — output tf32-rounded (feeds mma GEMM)
// ============================================================
__global__ void __launch_bounds__(256)
ffn_mid_kernel(const float* __restrict__ h, const float* __restrict__ l1w,
               const float* __restrict__ l1b, const float* __restrict__ theta,
               float* __restrict__ mid)
{
    __shared__ float sw[FF][9];
    __shared__ float sb[FF];
    __shared__ float scq[32][8];
    const int tid = threadIdx.x;
    const int m0 = blockIdx.x * 32;

    for (int i = tid; i < FF * 8; i += 256) sw[i >> 3][i & 7] = l1w[i];
    for (int i = tid; i < FF;     i += 256) sb[i] = l1b[i];
    {
        int r = tid >> 3, q = tid & 7;
        float hv = h[(size_t)(m0 + r) * EMB + q];
        scq[r][q] = cosf(hv) * cosf(theta[q]);
    }
    __syncthreads();

    for (int r = 0; r < 32; r++) {
        float c[8];
#pragma unroll
        for (int q = 0; q < 8; q++) c[q] = scq[r][q];
        float* mp = mid + (size_t)(m0 + r) * FF;
        for (int n = tid; n < FF; n += 256) {
            float acc = sb[n];
#pragma unroll
            for (int q = 0; q < 8; q++) acc += c[q] * sw[n][q];
            mp[n] = rtf32(fmaxf(acc, 0.f));
        }
    }
}

// ============================================================
// 7. Mean-pool + classifier
// ============================================================
__global__ void __launch_bounds__(256)
pool_cls_kernel(const float* __restrict__ h, const float* __restrict__ cw,
                const float* __restrict__ cb, float* __restrict__ out)
{
    int b = blockIdx.x;
    int e = threadIdx.x;
    const float* hp = h + (size_t)b * SEQ * EMB + e;
    float s = 0.f;
    for (int t = 0; t < SEQ; t++) s += hp[(size_t)t * EMB];
    __shared__ float sp[EMB];
    sp[e] = s * (1.f / 196.f);
    __syncthreads();
    if (e < NCLS) {
        float acc = cb[e];
        const float* w = cw + e * EMB;
        for (int k = 0; k < EMB; k++) acc += sp[k] * w[k];
        out[b * NCLS + e] = acc;
    }
}

// ============================================================
// launcher
// ============================================================
extern "C" void kernel_launch(void* const* d_in, const int* in_sizes, int n_in,
                              void* d_out, int out_size)
{
    const float* x    = (const float*)d_in[0];
    const float* qfw  = (const float*)d_in[1];
    const float* qfb  = (const float*)d_in[2];
    const float* pww  = (const float*)d_in[3];
    const float* pwb  = (const float*)d_in[4];
    const float* embw = (const float*)d_in[5];
    const float* embb = (const float*)d_in[6];
    const float* inw  = (const float*)d_in[7];
    const float* inb  = (const float*)d_in[8];
    const float* outw = (const float*)d_in[9];
    const float* outb = (const float*)d_in[10];
    const float* thet = (const float*)d_in[11];
    const float* l1w  = (const float*)d_in[12];
    const float* l1b  = (const float*)d_in[13];
    const float* l2w  = (const float*)d_in[14];
    const float* l2b  = (const float*)d_in[15];
    const float* ln1g = (const float*)d_in[16];
    const float* ln1b = (const float*)d_in[17];
    const float* ln2g = (const float*)d_in[18];
    const float* ln2b = (const float*)d_in[19];
    const float* clsw = (const float*)d_in[20];
    const float* clsb = (const float*)d_in[21];
    float* out = (float*)d_out;

    float *h, *qkv, *attn, *tmp, *mid, *feat, *w_in, *w_out, *w_l2;
    cudaGetSymbolAddress((void**)&h,     g_h);
    cudaGetSymbolAddress((void**)&qkv,   g_qkv);
    cudaGetSymbolAddress((void**)&attn,  g_attn);
    cudaGetSymbolAddress((void**)&tmp,   g_tmp);
    cudaGetSymbolAddress((void**)&mid,   g_mid);
    cudaGetSymbolAddress((void**)&feat,  g_feat);
    cudaGetSymbolAddress((void**)&w_in,  g_w_in);
    cudaGetSymbolAddress((void**)&w_out, g_w_out);
    cudaGetSymbolAddress((void**)&w_l2,  g_w_l2);

    const int SMEM_ATTN = SEQ * HDIM * 4 * 2;           // 50176 B
    const int SMEM_GEMM = 4 * GBUF * 4;                 // 73728 B
    cudaFuncSetAttribute(attention_kernel,
                         cudaFuncAttributeMaxDynamicSharedMemorySize, SMEM_ATTN);
    cudaFuncSetAttribute(mma_gemm<false>,
                         cudaFuncAttributeMaxDynamicSharedMemorySize, SMEM_GEMM);
    cudaFuncSetAttribute(mma_gemm<true>,
                         cudaFuncAttributeMaxDynamicSharedMemorySize, SMEM_GEMM);

    // weight tf32 pre-rounding
    const int n_in_w  = NBLK * 3 * EMB * EMB;
    const int n_out_w = NBLK * EMB * EMB;
    const int n_l2_w  = NBLK * EMB * FF;
    tf32_cvt_kernel<<<(n_in_w  + 255) / 256, 256>>>(inw,  w_in,  n_in_w);
    tf32_cvt_kernel<<<(n_out_w + 255) / 256, 256>>>(outw, w_out, n_out_w);
    tf32_cvt_kernel<<<(n_l2_w  + 255) / 256, 256>>>(l2w,  w_l2,  n_l2_w);

    quanv_kernel<<<(TOK * 4 + 255) / 256, 256>>>(x, qfw, qfb, pww, pwb, feat);
    embed_kernel<<<TOK, 256>>>(feat, embw, embb, h);

    for (int i = 0; i < NBLK; i++) {
        mma_gemm<false><<<dim3(3 * EMB / 128, TOK / 128), 256, SMEM_GEMM>>>(
            h, w_in + (size_t)i * 3 * EMB * EMB, inb + (size_t)i * 3 * EMB,
            nullptr, qkv, TOK, 3 * EMB, EMB);

        attention_kernel<<<dim3(HEADS, BATCH), 256, SMEM_ATTN>>>(qkv, attn);

        mma_gemm<true><<<dim3(EMB / 128, TOK / 128), 256, SMEM_GEMM>>>(
            attn, w_out + (size_t)i * EMB * EMB, outb + (size_t)i * EMB,
            h, tmp, TOK, EMB, EMB);
        ln_kernel<<<TOK / 8, 256>>>(tmp, ln1g + (size_t)i * EMB, ln1b + (size_t)i * EMB, h);

        ffn_mid_kernel<<<TOK / 32, 256>>>(h, l1w + (size_t)i * FF * NQBIT,
                                          l1b + (size_t)i * FF, thet + (size_t)i * NQBIT, mid);
        mma_gemm<true><<<dim3(EMB / 128, TOK / 128), 256, SMEM_GEMM>>>(
            mid, w_l2 + (size_t)i * EMB * FF, l2b + (size_t)i * EMB,
            h, tmp, TOK, EMB, FF);
        ln_kernel<<<TOK / 8, 256>>>(tmp, ln2g + (size_t)i * EMB, ln2b + (size_t)i * EMB, h);
    }

    pool_cls_kernel<<<BATCH, 256>>>(h, clsw, clsb, out);
}

// round 3
// speedup vs baseline: 2.4470x; 1.3956x over previous
#include <cuda_runtime.h>
#include <cuda_bf16.h>
#include <math.h>

// ---------------- problem constants ----------------
#define BATCH 256
#define SEQ   196
#define EMB   256
#define HEADS 8
#define HDIM  32
#define NBLK  4
#define FF    1024
#define NQBIT 8
#define NCLS  10
#define TOK   (BATCH*SEQ)          // 50176

// ---------------- device scratch ----------------
__device__ float g_h[(size_t)TOK * EMB];
__device__ float g_qkv[(size_t)TOK * 3 * EMB];
__device__ float g_attn[(size_t)TOK * EMB];
__device__ float g_tmp[(size_t)TOK * EMB];
__device__ float g_mid[(size_t)TOK * FF];
__device__ float g_feat[(size_t)TOK * 4];
__device__ float g_w_in[(size_t)NBLK * 3 * EMB * EMB];
__device__ float g_w_out[(size_t)NBLK * EMB * EMB];
__device__ float g_w_l2[(size_t)NBLK * EMB * FF];

// ---------------- helpers ----------------
__device__ __forceinline__ float rtf32(float x) {
    unsigned u;
    asm("cvt.rna.tf32.f32 %0, %1;" : "=r"(u) : "f"(x));
    return __uint_as_float(u);
}
__device__ __forceinline__ void cp_async16(void* smem, const void* gmem) {
    unsigned s = (unsigned)__cvta_generic_to_shared(smem);
    asm volatile("cp.async.ca.shared.global [%0], [%1], 16;" :: "r"(s), "l"(gmem));
}
__device__ __forceinline__ void cp_commit() { asm volatile("cp.async.commit_group;"); }
template<int N> __device__ __forceinline__ void cp_wait() {
    asm volatile("cp.async.wait_group %0;" :: "n"(N));
}
__device__ __forceinline__ void mma_tf32(float* c, const unsigned* a, unsigned b0, unsigned b1) {
    asm volatile(
        "mma.sync.aligned.m16n8k8.row.col.f32.tf32.tf32.f32 "
        "{%0,%1,%2,%3}, {%4,%5,%6,%7}, {%8,%9}, {%0,%1,%2,%3};"
        : "+f"(c[0]), "+f"(c[1]), "+f"(c[2]), "+f"(c[3])
        : "r"(a[0]), "r"(a[1]), "r"(a[2]), "r"(a[3]), "r"(b0), "r"(b1));
}

// ============================================================
// 0. weight tf32 rounding pre-pass
// ============================================================
__global__ void tf32_cvt_kernel(const float* __restrict__ src, float* __restrict__ dst, int n)
{
    int i = blockIdx.x * 256 + threadIdx.x;
    if (i < n) dst[i] = rtf32(src[i]);
}

// ============================================================
// 1. Quanvolution
// ============================================================
__global__ void quanv_kernel(const float* __restrict__ x,
                             const float* __restrict__ qw,
                             const float* __restrict__ qb,
                             const float* __restrict__ pw,
                             const float* __restrict__ pb,
                             float* __restrict__ feat)
{
    int idx = blockIdx.x * 256 + threadIdx.x;
    if (idx >= TOK * 4) return;
    int c  = idx & 3;
    int s  = (idx >> 2) % SEQ;
    int b  = idx / (SEQ * 4);
    int flat = s * 4 + c;
    int ch = flat / SEQ;
    int sp = flat % SEQ;
    int i  = sp / 14, j = sp % 14;

    float acc = pb[ch];
#pragma unroll
    for (int c2 = 0; c2 < 4; c2++) {
        const float* xb = x + (((size_t)b * 4 + c2) * 28 + 2 * i) * 28 + 2 * j;
        float conv = qb[c2]
                   + xb[0]  * qw[c2 * 4 + 0]
                   + xb[1]  * qw[c2 * 4 + 1]
                   + xb[28] * qw[c2 * 4 + 2]
                   + xb[29] * qw[c2 * 4 + 3];
        acc += pw[ch * 4 + c2] * conv;
    }
    feat[idx] = acc;
}

// ============================================================
// 2. Embedding + positional encoding (output tf32-rounded)
// ============================================================
__global__ void embed_kernel(const float* __restrict__ feat,
                             const float* __restrict__ ew,
                             const float* __restrict__ eb,
                             float* __restrict__ h)
{
    int m = blockIdx.x;
    int e = threadIdx.x;
    float4 f = *(const float4*)(feat + (size_t)m * 4);
    float4 w = *(const float4*)(ew + (size_t)e * 4);
    float acc = eb[e] + f.x * w.x + f.y * w.y + f.z * w.z + f.w * w.w;
    int s = m % SEQ;
    int p2 = e & ~1;
    float ang = (float)s * expf((float)p2 * (-9.210340371976184f / 256.0f));
    acc += (e & 1) ? cosf(ang) : sinf(ang);
    h[(size_t)m * EMB + e] = rtf32(acc);
}

// ============================================================
// 3. tf32 tensor-core GEMM (NT)
// ============================================================
#define GK 36
#define GBUF (128*GK)

template<bool RESID>
__global__ void __launch_bounds__(256, 2)
mma_gemm(const float* __restrict__ A, const float* __restrict__ W,
         const float* __restrict__ bias, const float* __restrict__ resid,
         float* __restrict__ C, int M, int N, int K)
{
    extern __shared__ float sm[];
    float* sA = sm;
    float* sW = sm + 2 * GBUF;

    const int tid  = threadIdx.x;
    const int bm   = blockIdx.y * 128;
    const int bn   = blockIdx.x * 128;
    const int lane = tid & 31;
    const int wid  = tid >> 5;
    const int wm   = (wid & 1) * 64;
    const int wn   = (wid >> 1) * 32;
    const int ln4  = lane >> 2;
    const int lnm  = lane & 3;

    const int r  = tid >> 1;
    const int kb = (tid & 1) * 16;
    const float* Ag = A + (size_t)(bm + r) * K + kb;
    const float* Wg = W + (size_t)(bn + r) * K + kb;

    float acc[4][4][4];
#pragma unroll
    for (int i = 0; i < 4; i++)
#pragma unroll
        for (int j = 0; j < 4; j++)
#pragma unroll
            for (int t = 0; t < 4; t++) acc[i][j][t] = 0.f;

    const int nc = K >> 5;

    {
        float* aw = sA + r * GK + kb;
        float* ww = sW + r * GK + kb;
#pragma unroll
        for (int q = 0; q < 4; q++) {
            cp_async16(aw + q * 4, Ag + q * 4);
            cp_async16(ww + q * 4, Wg + q * 4);
        }
        cp_commit();
    }

    for (int c = 0; c < nc; c++) {
        const int buf = c & 1;
        if (c + 1 < nc) {
            const int nb = buf ^ 1;
            const float* Ag2 = Ag + (c + 1) * 32;
            const float* Wg2 = Wg + (c + 1) * 32;
            float* aw = sA + nb * GBUF + r * GK + kb;
            float* ww = sW + nb * GBUF + r * GK + kb;
#pragma unroll
            for (int q = 0; q < 4; q++) {
                cp_async16(aw + q * 4, Ag2 + q * 4);
                cp_async16(ww + q * 4, Wg2 + q * 4);
            }
            cp_commit();
            cp_wait<1>();
        } else {
            cp_wait<0>();
        }
        __syncthreads();

        const float* cA = sA + buf * GBUF;
        const float* cW = sW + buf * GBUF;

#pragma unroll
        for (int s = 0; s < 4; s++) {
            const int k0 = s * 8;
            unsigned af[4][4], bf[4][2];
#pragma unroll
            for (int i = 0; i < 4; i++) {
                const float* p = cA + (wm + i * 16 + ln4) * GK + k0 + lnm;
                af[i][0] = __float_as_uint(p[0]);
                af[i][1] = __float_as_uint(p[8 * GK]);
                af[i][2] = __float_as_uint(p[4]);
                af[i][3] = __float_as_uint(p[8 * GK + 4]);
            }
#pragma unroll
            for (int j = 0; j < 4; j++) {
                const float* p = cW + (wn + j * 8 + ln4) * GK + k0 + lnm;
                bf[j][0] = __float_as_uint(p[0]);
                bf[j][1] = __float_as_uint(p[4]);
            }
#pragma unroll
            for (int i = 0; i < 4; i++)
#pragma unroll
                for (int j = 0; j < 4; j++)
                    mma_tf32(acc[i][j], af[i], bf[j][0], bf[j][1]);
        }
        __syncthreads();
    }

#pragma unroll
    for (int i = 0; i < 4; i++) {
        const int row0 = bm + wm + i * 16 + ln4;
#pragma unroll
        for (int j = 0; j < 4; j++) {
            const int col = bn + wn + j * 8 + 2 * lnm;
            const float b0 = bias[col], b1 = bias[col + 1];
            float2 v0 = make_float2(acc[i][j][0] + b0, acc[i][j][1] + b1);
            float2 v1 = make_float2(acc[i][j][2] + b0, acc[i][j][3] + b1);
            if (RESID) {
                float2 r0 = *(const float2*)(resid + (size_t)row0 * N + col);
                float2 r1 = *(const float2*)(resid + (size_t)(row0 + 8) * N + col);
                v0.x += r0.x; v0.y += r0.y;
                v1.x += r1.x; v1.y += r1.y;
            }
            *(float2*)(C + (size_t)row0 * N + col)       = v0;
            *(float2*)(C + (size_t)(row0 + 8) * N + col) = v1;
        }
    }
}

// ============================================================
// 4. Tensor-core attention. One CTA per (head,batch), 8 warps.
//    Scores: Q[16,32] x K^T via m16n8k8 tf32; full row in regs;
//    softmax; P routed through per-warp smem to PV mma.
//    smem: Ks[208][36], Vt[32][228], Ps[8][16][68]  (93,952 B)
// ============================================================
#define KS_STRIDE 36
#define VT_STRIDE 228
#define PS_STRIDE 68

__global__ void __launch_bounds__(256, 1)
attention_tc(const float* __restrict__ qkv, float* __restrict__ o)
{
    extern __shared__ float sm[];
    float* Ks = sm;                         // [208][36]
    float* Vt = Ks + 208 * KS_STRIDE;       // [32][228]
    float* Ps = Vt + 32 * VT_STRIDE;        // [8][16][68]

    const int hh = blockIdx.x;
    const int b  = blockIdx.y;
    const int tid  = threadIdx.x;
    const int lane = tid & 31;
    const int wid  = tid >> 5;
    const int r    = lane >> 2;     // 0..7
    const int lq   = lane & 3;      // 0..3
    const float scale = 0.17677669529663687f;   // 1/sqrt(32)
    const float* base = qkv + (size_t)b * SEQ * (3 * EMB) + hh * HDIM;

    // ---- stage K (tf32) with zero pad rows 196..207 ----
    for (int i = tid; i < 208 * 8; i += 256) {
        int s = i >> 3, d4 = (i & 7) << 2;
        float4 v = make_float4(0.f, 0.f, 0.f, 0.f);
        if (s < SEQ) v = *(const float4*)(base + (size_t)s * (3 * EMB) + EMB + d4);
        float* dst = Ks + s * KS_STRIDE + d4;
        dst[0] = rtf32(v.x); dst[1] = rtf32(v.y);
        dst[2] = rtf32(v.z); dst[3] = rtf32(v.w);
    }
    // ---- stage V transposed (tf32) ----
    for (int i = tid; i < SEQ * 32; i += 256) {
        int s = i >> 5, d = i & 31;
        Vt[d * VT_STRIDE + s] = rtf32(base[(size_t)s * (3 * EMB) + 2 * EMB + d]);
    }
    // zero V pad cols 196..207
    if (tid < 32 * 12) {
        int d = tid / 12, c = SEQ + tid % 12;
        Vt[d * VT_STRIDE + c] = 0.f;
    }
    __syncthreads();

    float* Pw = Ps + wid * 16 * PS_STRIDE;

    for (int strip = wid; strip < 13; strip += 8) {
        const int q0 = strip * 16 + r;
        const int q1 = q0 + 8;
        const int qa = q0 < SEQ ? q0 : SEQ - 1;
        const int qb = q1 < SEQ ? q1 : SEQ - 1;

        // Q fragments (scaled, tf32)
        unsigned af[4][4];
#pragma unroll
        for (int kc = 0; kc < 4; kc++) {
            const float* pa = base + (size_t)qa * (3 * EMB) + kc * 8 + lq;
            const float* pc = base + (size_t)qb * (3 * EMB) + kc * 8 + lq;
            af[kc][0] = __float_as_uint(rtf32(pa[0] * scale));
            af[kc][1] = __float_as_uint(rtf32(pc[0] * scale));
            af[kc][2] = __float_as_uint(rtf32(pa[4] * scale));
            af[kc][3] = __float_as_uint(rtf32(pc[4] * scale));
        }

        // ---- scores ----
        float acc[26][4];
#pragma unroll
        for (int j = 0; j < 26; j++) {
            acc[j][0] = 0.f; acc[j][1] = 0.f; acc[j][2] = 0.f; acc[j][3] = 0.f;
        }
#pragma unroll
        for (int j = 0; j < 25; j++) {
            const float* kbp = Ks + (j * 8 + r) * KS_STRIDE + lq;
#pragma unroll
            for (int kc = 0; kc < 4; kc++) {
                unsigned b0 = __float_as_uint(kbp[kc * 8]);
                unsigned b1 = __float_as_uint(kbp[kc * 8 + 4]);
                mma_tf32(acc[j], af[kc], b0, b1);
            }
        }
        // mask padded keys
        if (lq >= 2) {
            acc[24][0] = -1e30f; acc[24][1] = -1e30f;
            acc[24][2] = -1e30f; acc[24][3] = -1e30f;
        }
        acc[25][0] = -1e30f; acc[25][1] = -1e30f;
        acc[25][2] = -1e30f; acc[25][3] = -1e30f;

        // ---- softmax (rows r and r+8) ----
        float m0 = -1e30f, m1 = -1e30f;
#pragma unroll
        for (int j = 0; j < 26; j++) {
            m0 = fmaxf(m0, fmaxf(acc[j][0], acc[j][1]));
            m1 = fmaxf(m1, fmaxf(acc[j][2], acc[j][3]));
        }
        m0 = fmaxf(m0, __shfl_xor_sync(0xffffffffu, m0, 1));
        m0 = fmaxf(m0, __shfl_xor_sync(0xffffffffu, m0, 2));
        m1 = fmaxf(m1, __shfl_xor_sync(0xffffffffu, m1, 1));
        m1 = fmaxf(m1, __shfl_xor_sync(0xffffffffu, m1, 2));
        float l0 = 0.f, l1 = 0.f;
#pragma unroll
        for (int j = 0; j < 26; j++) {
            acc[j][0] = __expf(acc[j][0] - m0);
            acc[j][1] = __expf(acc[j][1] - m0);
            acc[j][2] = __expf(acc[j][2] - m1);
            acc[j][3] = __expf(acc[j][3] - m1);
            l0 += acc[j][0] + acc[j][1];
            l1 += acc[j][2] + acc[j][3];
        }
        l0 += __shfl_xor_sync(0xffffffffu, l0, 1);
        l0 += __shfl_xor_sync(0xffffffffu, l0, 2);
        l1 += __shfl_xor_sync(0xffffffffu, l1, 1);
        l1 += __shfl_xor_sync(0xffffffffu, l1, 2);
        const float inv0 = 1.f / l0;
        const float inv1 = 1.f / l1;

        // ---- P @ V, in key-chunks of 64 via per-warp smem buffer ----
        float O[4][4];
#pragma unroll
        for (int nt = 0; nt < 4; nt++) {
            O[nt][0] = 0.f; O[nt][1] = 0.f; O[nt][2] = 0.f; O[nt][3] = 0.f;
        }
#pragma unroll
        for (int ch = 0; ch < 4; ch++) {
            const int njt = (ch < 3) ? 8 : 2;
#pragma unroll
            for (int jj = 0; jj < 8; jj++) {
                if (jj < njt) {
                    const int j = ch * 8 + jj;
                    float* p0 = Pw + r * PS_STRIDE + jj * 8 + 2 * lq;
                    float* p1 = Pw + (r + 8) * PS_STRIDE + jj * 8 + 2 * lq;
                    p0[0] = rtf32(acc[j][0]); p0[1] = rtf32(acc[j][1]);
                    p1[0] = rtf32(acc[j][2]); p1[1] = rtf32(acc[j][3]);
                }
            }
            __syncwarp();
            const int nkk = (ch < 3) ? 8 : 2;
#pragma unroll
            for (int kk = 0; kk < 8; kk++) {
                if (kk < nkk) {
                    unsigned pa[4];
                    pa[0] = __float_as_uint(Pw[r * PS_STRIDE + kk * 8 + lq]);
                    pa[1] = __float_as_uint(Pw[(r + 8) * PS_STRIDE + kk * 8 + lq]);
                    pa[2] = __float_as_uint(Pw[r * PS_STRIDE + kk * 8 + lq + 4]);
                    pa[3] = __float_as_uint(Pw[(r + 8) * PS_STRIDE + kk * 8 + lq + 4]);
                    const float* vbp = Vt + r * VT_STRIDE + ch * 64 + kk * 8 + lq;
#pragma unroll
                    for (int nt = 0; nt < 4; nt++) {
                        unsigned b0 = __float_as_uint(vbp[nt * 8 * VT_STRIDE]);
                        unsigned b1 = __float_as_uint(vbp[nt * 8 * VT_STRIDE + 4]);
                        mma_tf32(O[nt], pa, b0, b1);
                    }
                }
            }
            __syncwarp();
        }

        // ---- epilogue (tf32-rounded: feeds next GEMM) ----
        if (q0 < SEQ) {
            float* op = o + (size_t)(b * SEQ + q0) * EMB + hh * HDIM + 2 * lq;
#pragma unroll
            for (int nt = 0; nt < 4; nt++) {
                float2 v = make_float2(rtf32(O[nt][0] * inv0), rtf32(O[nt][1] * inv0));
                *(float2*)(op + nt * 8) = v;
            }
        }
        if (q1 < SEQ) {
            float* op = o + (size_t)(b * SEQ + q1) * EMB + hh * HDIM + 2 * lq;
#pragma unroll
            for (int nt = 0; nt < 4; nt++) {
                float2 v = make_float2(rtf32(O[nt][2] * inv1), rtf32(O[nt][3] * inv1));
                *(float2*)(op + nt * 8) = v;
            }
        }
    }
}
#define SMEM_ATTN_TC ((208*KS_STRIDE + 32*VT_STRIDE + 8*16*PS_STRIDE) * 4)

// ============================================================
// 5. LayerNorm (output tf32-rounded)
// ============================================================
__global__ void __launch_bounds__(256)
ln_kernel(const float* __restrict__ x, const float* __restrict__ g,
          const float* __restrict__ b, float* __restrict__ y)
{
    int row  = blockIdx.x * 8 + (threadIdx.x >> 5);
    int lane = threadIdx.x & 31;
    const float* xr = x + (size_t)row * EMB;
    float v[8];
    float s = 0.f;
#pragma unroll
    for (int i = 0; i < 8; i++) { v[i] = xr[i * 32 + lane]; s += v[i]; }
#pragma unroll
    for (int o = 16; o > 0; o >>= 1) s += __shfl_xor_sync(0xffffffffu, s, o);
    float mean = s * (1.f / 256.f);
    float q = 0.f;
#pragma unroll
    for (int i = 0; i < 8; i++) { float d = v[i] - mean; q += d * d; }
#pragma unroll
    for (int o = 16; o > 0; o >>= 1) q += __shfl_xor_sync(0xffffffffu, q, o);
    float rstd = rsqrtf(q * (1.f / 256.f) + 1e-5f);
    float* yr = y + (size_t)row * EMB;
#pragma unroll
    for (int i = 0; i < 8; i++) {
        int c = i * 32 + lane;
        yr[c] = rtf32((v[i] - mean) * rstd * g[c] + b[c]);
    }
}

// ============================================================
// 6. Quantum FFN mid (output tf32-rounded)
// ============================================================
__global__ void __launch_bounds__(256)
ffn_mid_kernel(const float* __restrict__ h, const float* __restrict__ l1w,
               const float* __restrict__ l1b, const float* __restrict__ theta,
               float* __restrict__ mid)
{
    __shared__ float sw[FF][9];
    __shared__ float sb[FF];
    __shared__ float scq[32][8];
    const int tid = threadIdx.x;
    const int m0 = blockIdx.x * 32;

    for (int i = tid; i < FF * 8; i += 256) sw[i >> 3][i & 7] = l1w[i];
    for (int i = tid; i < FF;     i += 256) sb[i] = l1b[i];
    {
        int r = tid >> 3, q = tid & 7;
        float hv = h[(size_t)(m0 + r) * EMB + q];
        scq[r][q] = cosf(hv) * cosf(theta[q]);
    }
    __syncthreads();

    for (int r = 0; r < 32; r++) {
        float c[8];
#pragma unroll
        for (int q = 0; q < 8; q++) c[q] = scq[r][q];
        float* mp = mid + (size_t)(m0 + r) * FF;
        for (int n = tid; n < FF; n += 256) {
            float acc = sb[n];
#pragma unroll
            for (int q = 0; q < 8; q++) acc += c[q] * sw[n][q];
            mp[n] = rtf32(fmaxf(acc, 0.f));
        }
    }
}

// ============================================================
// 7. Mean-pool + classifier
// ============================================================
__global__ void __launch_bounds__(256)
pool_cls_kernel(const float* __restrict__ h, const float* __restrict__ cw,
                const float* __restrict__ cb, float* __restrict__ out)
{
    int b = blockIdx.x;
    int e = threadIdx.x;
    const float* hp = h + (size_t)b * SEQ * EMB + e;
    float s = 0.f;
    for (int t = 0; t < SEQ; t++) s += hp[(size_t)t * EMB];
    __shared__ float sp[EMB];
    sp[e] = s * (1.f / 196.f);
    __syncthreads();
    if (e < NCLS) {
        float acc = cb[e];
        const float* w = cw + e * EMB;
        for (int k = 0; k < EMB; k++) acc += sp[k] * w[k];
        out[b * NCLS + e] = acc;
    }
}

// ============================================================
// launcher
// ============================================================
extern "C" void kernel_launch(void* const* d_in, const int* in_sizes, int n_in,
                              void* d_out, int out_size)
{
    const float* x    = (const float*)d_in[0];
    const float* qfw  = (const float*)d_in[1];
    const float* qfb  = (const float*)d_in[2];
    const float* pww  = (const float*)d_in[3];
    const float* pwb  = (const float*)d_in[4];
    const float* embw = (const float*)d_in[5];
    const float* embb = (const float*)d_in[6];
    const float* inw  = (const float*)d_in[7];
    const float* inb  = (const float*)d_in[8];
    const float* outw = (const float*)d_in[9];
    const float* outb = (const float*)d_in[10];
    const float* thet = (const float*)d_in[11];
    const float* l1w  = (const float*)d_in[12];
    const float* l1b  = (const float*)d_in[13];
    const float* l2w  = (const float*)d_in[14];
    const float* l2b  = (const float*)d_in[15];
    const float* ln1g = (const float*)d_in[16];
    const float* ln1b = (const float*)d_in[17];
    const float* ln2g = (const float*)d_in[18];
    const float* ln2b = (const float*)d_in[19];
    const float* clsw = (const float*)d_in[20];
    const float* clsb = (const float*)d_in[21];
    float* out = (float*)d_out;

    float *h, *qkv, *attn, *tmp, *mid, *feat, *w_in, *w_out, *w_l2;
    cudaGetSymbolAddress((void**)&h,     g_h);
    cudaGetSymbolAddress((void**)&qkv,   g_qkv);
    cudaGetSymbolAddress((void**)&attn,  g_attn);
    cudaGetSymbolAddress((void**)&tmp,   g_tmp);
    cudaGetSymbolAddress((void**)&mid,   g_mid);
    cudaGetSymbolAddress((void**)&feat,  g_feat);
    cudaGetSymbolAddress((void**)&w_in,  g_w_in);
    cudaGetSymbolAddress((void**)&w_out, g_w_out);
    cudaGetSymbolAddress((void**)&w_l2,  g_w_l2);

    const int SMEM_GEMM = 4 * GBUF * 4;
    cudaFuncSetAttribute(attention_tc,
                         cudaFuncAttributeMaxDynamicSharedMemorySize, SMEM_ATTN_TC);
    cudaFuncSetAttribute(mma_gemm<false>,
                         cudaFuncAttributeMaxDynamicSharedMemorySize, SMEM_GEMM);
    cudaFuncSetAttribute(mma_gemm<true>,
                         cudaFuncAttributeMaxDynamicSharedMemorySize, SMEM_GEMM);

    const int n_in_w  = NBLK * 3 * EMB * EMB;
    const int n_out_w = NBLK * EMB * EMB;
    const int n_l2_w  = NBLK * EMB * FF;
    tf32_cvt_kernel<<<(n_in_w  + 255) / 256, 256>>>(inw,  w_in,  n_in_w);
    tf32_cvt_kernel<<<(n_out_w + 255) / 256, 256>>>(outw, w_out, n_out_w);
    tf32_cvt_kernel<<<(n_l2_w  + 255) / 256, 256>>>(l2w,  w_l2,  n_l2_w);

    quanv_kernel<<<(TOK * 4 + 255) / 256, 256>>>(x, qfw, qfb, pww, pwb, feat);
    embed_kernel<<<TOK, 256>>>(feat, embw, embb, h);

    for (int i = 0; i < NBLK; i++) {
        mma_gemm<false><<<dim3(3 * EMB / 128, TOK / 128), 256, SMEM_GEMM>>>(
            h, w_in + (size_t)i * 3 * EMB * EMB, inb + (size_t)i * 3 * EMB,
            nullptr, qkv, TOK, 3 * EMB, EMB);

        attention_tc<<<dim3(HEADS, BATCH), 256, SMEM_ATTN_TC>>>(qkv, attn);

        mma_gemm<true><<<dim3(EMB / 128, TOK / 128), 256, SMEM_GEMM>>>(
            attn, w_out + (size_t)i * EMB * EMB, outb + (size_t)i * EMB,
            h, tmp, TOK, EMB, EMB);
        ln_kernel<<<TOK / 8, 256>>>(tmp, ln1g + (size_t)i * EMB, ln1b + (size_t)i * EMB, h);

        ffn_mid_kernel<<<TOK / 32, 256>>>(h, l1w + (size_t)i * FF * NQBIT,
                                          l1b + (size_t)i * FF, thet + (size_t)i * NQBIT, mid);
        mma_gemm<true><<<dim3(EMB / 128, TOK / 128), 256, SMEM_GEMM>>>(
            mid, w_l2 + (size_t)i * EMB * FF, l2b + (size_t)i * EMB,
            h, tmp, TOK, EMB, FF);
        ln_kernel<<<TOK / 8, 256>>>(tmp, ln2g + (size_t)i * EMB, ln2b + (size_t)i * EMB, h);
    }

    pool_cls_kernel<<<BATCH, 256>>>(h, clsw, clsb, out);
}

// round 4
// speedup vs baseline: 2.5244x; 1.0316x over previous
#include <cuda_runtime.h>
#include <cuda_bf16.h>
#include <math.h>

// ---------------- problem constants ----------------
#define BATCH 256
#define SEQ   196
#define EMB   256
#define HEADS 8
#define HDIM  32
#define NBLK  4
#define FF    1024
#define NQBIT 8
#define NCLS  10
#define TOK   (BATCH*SEQ)          // 50176

// ---------------- device scratch ----------------
__device__ float g_h[(size_t)TOK * EMB];
__device__ float g_qkv[(size_t)TOK * 3 * EMB];
__device__ float g_attn[(size_t)TOK * EMB];
__device__ float g_feat[(size_t)TOK * 4];
__device__ float g_w_in[(size_t)NBLK * 3 * EMB * EMB];
__device__ float g_w_out[(size_t)NBLK * EMB * EMB];
__device__ float g_w_l2[(size_t)NBLK * EMB * FF];

// ---------------- helpers ----------------
__device__ __forceinline__ float rtf32(float x) {
    unsigned u;
    asm("cvt.rna.tf32.f32 %0, %1;" : "=r"(u) : "f"(x));
    return __uint_as_float(u);
}
__device__ __forceinline__ void cp_async16(void* smem, const void* gmem) {
    unsigned s = (unsigned)__cvta_generic_to_shared(smem);
    asm volatile("cp.async.ca.shared.global [%0], [%1], 16;" :: "r"(s), "l"(gmem));
}
__device__ __forceinline__ void cp_commit() { asm volatile("cp.async.commit_group;"); }
template<int N> __device__ __forceinline__ void cp_wait() {
    asm volatile("cp.async.wait_group %0;" :: "n"(N));
}
__device__ __forceinline__ void mma_tf32(float* c, const unsigned* a, unsigned b0, unsigned b1) {
    asm volatile(
        "mma.sync.aligned.m16n8k8.row.col.f32.tf32.tf32.f32 "
        "{%0,%1,%2,%3}, {%4,%5,%6,%7}, {%8,%9}, {%0,%1,%2,%3};"
        : "+f"(c[0]), "+f"(c[1]), "+f"(c[2]), "+f"(c[3])
        : "r"(a[0]), "r"(a[1]), "r"(a[2]), "r"(a[3]), "r"(b0), "r"(b1));
}

// ============================================================
// 0. weight tf32 rounding pre-pass
// ============================================================
__global__ void tf32_cvt_kernel(const float* __restrict__ src, float* __restrict__ dst, int n)
{
    int i = blockIdx.x * 256 + threadIdx.x;
    if (i < n) dst[i] = rtf32(src[i]);
}

// ============================================================
// 1. Quanvolution
// ============================================================
__global__ void quanv_kernel(const float* __restrict__ x,
                             const float* __restrict__ qw,
                             const float* __restrict__ qb,
                             const float* __restrict__ pw,
                             const float* __restrict__ pb,
                             float* __restrict__ feat)
{
    int idx = blockIdx.x * 256 + threadIdx.x;
    if (idx >= TOK * 4) return;
    int c  = idx & 3;
    int s  = (idx >> 2) % SEQ;
    int b  = idx / (SEQ * 4);
    int flat = s * 4 + c;
    int ch = flat / SEQ;
    int sp = flat % SEQ;
    int i  = sp / 14, j = sp % 14;

    float acc = pb[ch];
#pragma unroll
    for (int c2 = 0; c2 < 4; c2++) {
        const float* xb = x + (((size_t)b * 4 + c2) * 28 + 2 * i) * 28 + 2 * j;
        float conv = qb[c2]
                   + xb[0]  * qw[c2 * 4 + 0]
                   + xb[1]  * qw[c2 * 4 + 1]
                   + xb[28] * qw[c2 * 4 + 2]
                   + xb[29] * qw[c2 * 4 + 3];
        acc += pw[ch * 4 + c2] * conv;
    }
    feat[idx] = acc;
}

// ============================================================
// 2. Embedding + positional encoding (output tf32-rounded)
// ============================================================
__global__ void embed_kernel(const float* __restrict__ feat,
                             const float* __restrict__ ew,
                             const float* __restrict__ eb,
                             float* __restrict__ h)
{
    int m = blockIdx.x;
    int e = threadIdx.x;
    float4 f = *(const float4*)(feat + (size_t)m * 4);
    float4 w = *(const float4*)(ew + (size_t)e * 4);
    float acc = eb[e] + f.x * w.x + f.y * w.y + f.z * w.z + f.w * w.w;
    int s = m % SEQ;
    int p2 = e & ~1;
    float ang = (float)s * expf((float)p2 * (-9.210340371976184f / 256.0f));
    acc += (e & 1) ? cosf(ang) : sinf(ang);
    h[(size_t)m * EMB + e] = rtf32(acc);
}

// ============================================================
// 3. tf32 tensor-core GEMM, CTA tile 128x256, 8 warps @ 64x64.
//    ASRC: 0 = load A via cp.async;  1 = A computed on the fly:
//          A = relu( (cos(h[:, :8])*cos(theta)) @ l1w^T + l1b )  [quantum FFN]
//    EPI:  0 = bias only (write C);  1 = bias + resid + LayerNorm (write C,
//          in-place with resid allowed; requires N == 256, bn == 0)
// ============================================================
#define GK 36
#define A_BUF (128*GK)   // 4608 floats
#define B_BUF (256*GK)   // 9216 floats
// smem float offsets
#define OFF_SB    (2*A_BUF)                 // 9216
#define OFF_BIAS  (OFF_SB + 2*B_BUF)        // 27648
#define OFF_G     (OFF_BIAS + 256)          // 27904
#define OFF_BL    (OFF_G + 256)             // 28160
#define OFF_RED   (OFF_BL + 256)            // 28416 (float2[128][4] = 1024 floats)
#define OFF_QM    (OFF_RED + 1024)          // 29440 ([128][8])
#define OFF_SL    (OFF_QM + 1024)           // 30464 ([2][32][8])
#define OFF_SLB   (OFF_SL + 512)            // 30976 ([2][32])
#define SMEM_G256 ((OFF_SLB + 64) * 4)      // 124160 bytes

template<int ASRC, int EPI>
__global__ void __launch_bounds__(256, 1)
gemm256(const float* __restrict__ A, const float* __restrict__ W,
        const float* __restrict__ bias, const float* __restrict__ resid,
        const float* __restrict__ lng, const float* __restrict__ lnbb,
        const float* __restrict__ l1w, const float* __restrict__ l1b,
        const float* __restrict__ theta,
        float* __restrict__ C, int M, int N, int K)
{
    extern __shared__ float sm[];
    float*  sA    = sm;
    float*  sB    = sm + OFF_SB;
    float*  sbias = sm + OFF_BIAS;
    float*  sg    = sm + OFF_G;
    float*  sbl   = sm + OFF_BL;
    float2* sred  = (float2*)(sm + OFF_RED);
    float*  qm    = sm + OFF_QM;
    float*  sL    = sm + OFF_SL;
    float*  slb   = sm + OFF_SLB;

    const int tid  = threadIdx.x;
    const int lane = tid & 31;
    const int wid  = tid >> 5;
    const int bm   = blockIdx.y * 128;
    const int bn   = blockIdx.x * 256;
    const int wm   = (wid & 1) * 64;
    const int wn   = (wid >> 1) * 64;
    const int ln4  = lane >> 2;
    const int lnm  = lane & 3;
    const int r    = tid >> 1;
    const int kb   = (tid & 1) * 16;

    sbias[tid] = bias[bn + tid];
    if (EPI == 1) { sg[tid] = lng[tid]; sbl[tid] = lnbb[tid]; }

    if (ASRC == 1) {
        if (tid < 128) {
            const float* hp = A + (size_t)(bm + tid) * EMB;
#pragma unroll
            for (int q = 0; q < 8; q++)
                qm[tid * 8 + q] = cosf(hp[q]) * cosf(theta[q]);
        }
        if (tid < 64) {
            int rr = tid >> 1, hf = (tid & 1) * 4;
            *(float4*)(sL + rr * 8 + hf) = *(const float4*)(l1w + rr * 8 + hf);
        }
        if (tid < 32) slb[tid] = l1b[tid];
    }

    float acc[4][8][4];
#pragma unroll
    for (int i = 0; i < 4; i++)
#pragma unroll
        for (int j = 0; j < 8; j++)
#pragma unroll
            for (int t = 0; t < 4; t++) acc[i][j][t] = 0.f;

    const int nc = K >> 5;
    const float* Wg = W + (size_t)(bn + tid) * K;

    // ---- prologue: chunk 0 ----
    {
        float* bw = sB + tid * GK;
#pragma unroll
        for (int q = 0; q < 8; q++) cp_async16(bw + q * 4, Wg + q * 4);
        if (ASRC == 0) {
            const float* Ag = A + (size_t)(bm + r) * K + kb;
            float* aw = sA + r * GK + kb;
#pragma unroll
            for (int q = 0; q < 4; q++) cp_async16(aw + q * 4, Ag + q * 4);
        }
        cp_commit();
    }
    if (ASRC == 1) {
        __syncthreads();     // qm, sL[0], slb[0] visible
        // compute A chunk 0 -> sA[0]
        float qv[8];
        *(float4*)qv       = *(const float4*)(qm + r * 8);
        *(float4*)(qv + 4) = *(const float4*)(qm + r * 8 + 4);
        float out[16];
#pragma unroll
        for (int j = 0; j < 16; j++) {
            int k = kb + j;
            const float* lr = sL + k * 8;
            float v = slb[k];
#pragma unroll
            for (int q = 0; q < 8; q++) v += qv[q] * lr[q];
            out[j] = rtf32(fmaxf(v, 0.f));
        }
        float* aw = sA + r * GK + kb;
#pragma unroll
        for (int j4 = 0; j4 < 4; j4++)
            *(float4*)(aw + j4 * 4) = *(float4*)(out + j4 * 4);
    }

    // ---- main loop ----
    for (int c = 0; c < nc; c++) {
        const int buf = c & 1;
        const int nb  = buf ^ 1;
        if (c + 1 < nc) {
            const float* Wg2 = Wg + (c + 1) * 32;
            float* bw = sB + nb * B_BUF + tid * GK;
#pragma unroll
            for (int q = 0; q < 8; q++) cp_async16(bw + q * 4, Wg2 + q * 4);
            if (ASRC == 0) {
                const float* Ag2 = A + (size_t)(bm + r) * K + (c + 1) * 32 + kb;
                float* aw = sA + nb * A_BUF + r * GK + kb;
#pragma unroll
                for (int q = 0; q < 4; q++) cp_async16(aw + q * 4, Ag2 + q * 4);
            } else {
                if (tid < 64) {
                    int rr = tid >> 1, hf = (tid & 1) * 4;
                    *(float4*)(sL + nb * 256 + rr * 8 + hf) =
                        *(const float4*)(l1w + ((size_t)(c + 1) * 32 + rr) * 8 + hf);
                }
                if (tid < 32) slb[nb * 32 + tid] = l1b[(c + 1) * 32 + tid];
            }
            cp_commit();
            cp_wait<1>();
        } else {
            cp_wait<0>();
        }
        __syncthreads();    // sA[buf]/sB[buf] ready; sL[nb] visible

        const float* cA = sA + buf * A_BUF;
        const float* cB = sB + buf * B_BUF;
#pragma unroll
        for (int s = 0; s < 4; s++) {
            const int k0 = s * 8;
            unsigned af[4][4];
#pragma unroll
            for (int i = 0; i < 4; i++) {
                const float* p = cA + (wm + i * 16 + ln4) * GK + k0 + lnm;
                af[i][0] = __float_as_uint(p[0]);
                af[i][1] = __float_as_uint(p[8 * GK]);
                af[i][2] = __float_as_uint(p[4]);
                af[i][3] = __float_as_uint(p[8 * GK + 4]);
            }
#pragma unroll
            for (int j = 0; j < 8; j++) {
                const float* p = cB + (wn + j * 8 + ln4) * GK + k0 + lnm;
                unsigned b0 = __float_as_uint(p[0]);
                unsigned b1 = __float_as_uint(p[4]);
#pragma unroll
                for (int i = 0; i < 4; i++)
                    mma_tf32(acc[i][j], af[i], b0, b1);
            }
        }

        if (ASRC == 1 && c + 1 < nc) {
            // compute A chunk c+1 -> sA[nb]
            float qv[8];
            *(float4*)qv       = *(const float4*)(qm + r * 8);
            *(float4*)(qv + 4) = *(const float4*)(qm + r * 8 + 4);
            float out[16];
#pragma unroll
            for (int j = 0; j < 16; j++) {
                int k = kb + j;
                const float* lr = sL + nb * 256 + k * 8;
                float v = slb[nb * 32 + k];
#pragma unroll
                for (int q = 0; q < 8; q++) v += qv[q] * lr[q];
                out[j] = rtf32(fmaxf(v, 0.f));
            }
            float* aw = sA + nb * A_BUF + r * GK + kb;
#pragma unroll
            for (int j4 = 0; j4 < 4; j4++)
                *(float4*)(aw + j4 * 4) = *(float4*)(out + j4 * 4);
        }
        __syncthreads();    // protect sA[nb] STS & buffer reuse
    }

    // ---- epilogue ----
    if (EPI == 0) {
#pragma unroll
        for (int i = 0; i < 4; i++) {
            const int gr0 = bm + wm + i * 16 + ln4;
#pragma unroll
            for (int j = 0; j < 8; j++) {
                const int col = wn + j * 8 + 2 * lnm;
                const float b0 = sbias[col], b1 = sbias[col + 1];
                float2 v0 = make_float2(acc[i][j][0] + b0, acc[i][j][1] + b1);
                float2 v1 = make_float2(acc[i][j][2] + b0, acc[i][j][3] + b1);
                *(float2*)(C + (size_t)gr0 * N + bn + col)       = v0;
                *(float2*)(C + (size_t)(gr0 + 8) * N + bn + col) = v1;
            }
        }
    } else {
        // bias + residual, per-row partial stats
#pragma unroll
        for (int i = 0; i < 4; i++) {
            const int lr0 = wm + i * 16 + ln4;
            const int gr0 = bm + lr0;
            float s0 = 0.f, q0 = 0.f, s1 = 0.f, q1 = 0.f;
#pragma unroll
            for (int j = 0; j < 8; j++) {
                const int col = wn + j * 8 + 2 * lnm;
                const float b0 = sbias[col], b1 = sbias[col + 1];
                float2 r0 = *(const float2*)(resid + (size_t)gr0 * 256 + col);
                float2 r1 = *(const float2*)(resid + (size_t)(gr0 + 8) * 256 + col);
                float v0 = acc[i][j][0] + b0 + r0.x;
                float v1 = acc[i][j][1] + b1 + r0.y;
                float v2 = acc[i][j][2] + b0 + r1.x;
                float v3 = acc[i][j][3] + b1 + r1.y;
                acc[i][j][0] = v0; acc[i][j][1] = v1;
                acc[i][j][2] = v2; acc[i][j][3] = v3;
                s0 += v0 + v1; q0 += v0 * v0 + v1 * v1;
                s1 += v2 + v3; q1 += v2 * v2 + v3 * v3;
            }
#pragma unroll
            for (int o = 1; o <= 2; o <<= 1) {
                s0 += __shfl_xor_sync(0xffffffffu, s0, o);
                q0 += __shfl_xor_sync(0xffffffffu, q0, o);
                s1 += __shfl_xor_sync(0xffffffffu, s1, o);
                q1 += __shfl_xor_sync(0xffffffffu, q1, o);
            }
            if (lnm == 0) {
                sred[lr0 * 4 + (wid >> 1)]       = make_float2(s0, q0);
                sred[(lr0 + 8) * 4 + (wid >> 1)] = make_float2(s1, q1);
            }
        }
        __syncthreads();
#pragma unroll
        for (int i = 0; i < 4; i++) {
            const int lr0 = wm + i * 16 + ln4;
            const int gr0 = bm + lr0;
            float2 a0 = sred[lr0 * 4 + 0], a1 = sred[lr0 * 4 + 1];
            float2 a2 = sred[lr0 * 4 + 2], a3 = sred[lr0 * 4 + 3];
            float mean0 = (a0.x + a1.x + a2.x + a3.x) * (1.f / 256.f);
            float e0    = (a0.y + a1.y + a2.y + a3.y) * (1.f / 256.f);
            float rstd0 = rsqrtf(e0 - mean0 * mean0 + 1e-5f);
            float2 c0 = sred[(lr0 + 8) * 4 + 0], c1 = sred[(lr0 + 8) * 4 + 1];
            float2 c2 = sred[(lr0 + 8) * 4 + 2], c3 = sred[(lr0 + 8) * 4 + 3];
            float mean1 = (c0.x + c1.x + c2.x + c3.x) * (1.f / 256.f);
            float e1    = (c0.y + c1.y + c2.y + c3.y) * (1.f / 256.f);
            float rstd1 = rsqrtf(e1 - mean1 * mean1 + 1e-5f);
#pragma unroll
            for (int j = 0; j < 8; j++) {
                const int col = wn + j * 8 + 2 * lnm;
                const float g0 = sg[col], g1 = sg[col + 1];
                const float d0 = sbl[col], d1 = sbl[col + 1];
                float2 y0, y1;
                y0.x = rtf32((acc[i][j][0] - mean0) * rstd0 * g0 + d0);
                y0.y = rtf32((acc[i][j][1] - mean0) * rstd0 * g1 + d1);
                y1.x = rtf32((acc[i][j][2] - mean1) * rstd1 * g0 + d0);
                y1.y = rtf32((acc[i][j][3] - mean1) * rstd1 * g1 + d1);
                *(float2*)(C + (size_t)gr0 * 256 + col)       = y0;
                *(float2*)(C + (size_t)(gr0 + 8) * 256 + col) = y1;
            }
        }
    }
}

// ============================================================
// 4. Tensor-core attention (unchanged from R3)
// ============================================================
#define KS_STRIDE 36
#define VT_STRIDE 228
#define PS_STRIDE 68

__global__ void __launch_bounds__(256, 1)
attention_tc(const float* __restrict__ qkv, float* __restrict__ o)
{
    extern __shared__ float sma[];
    float* Ks = sma;
    float* Vt = Ks + 208 * KS_STRIDE;
    float* Ps = Vt + 32 * VT_STRIDE;

    const int hh = blockIdx.x;
    const int b  = blockIdx.y;
    const int tid  = threadIdx.x;
    const int lane = tid & 31;
    const int wid  = tid >> 5;
    const int r    = lane >> 2;
    const int lq   = lane & 3;
    const float scale = 0.17677669529663687f;
    const float* base = qkv + (size_t)b * SEQ * (3 * EMB) + hh * HDIM;

    for (int i = tid; i < 208 * 8; i += 256) {
        int s = i >> 3, d4 = (i & 7) << 2;
        float4 v = make_float4(0.f, 0.f, 0.f, 0.f);
        if (s < SEQ) v = *(const float4*)(base + (size_t)s * (3 * EMB) + EMB + d4);
        float* dst = Ks + s * KS_STRIDE + d4;
        dst[0] = rtf32(v.x); dst[1] = rtf32(v.y);
        dst[2] = rtf32(v.z); dst[3] = rtf32(v.w);
    }
    for (int i = tid; i < SEQ * 32; i += 256) {
        int s = i >> 5, d = i & 31;
        Vt[d * VT_STRIDE + s] = rtf32(base[(size_t)s * (3 * EMB) + 2 * EMB + d]);
    }
    if (tid < 32 * 12) {
        int d = tid / 12, c = SEQ + tid % 12;
        Vt[d * VT_STRIDE + c] = 0.f;
    }
    __syncthreads();

    float* Pw = Ps + wid * 16 * PS_STRIDE;

    for (int strip = wid; strip < 13; strip += 8) {
        const int q0 = strip * 16 + r;
        const int q1 = q0 + 8;
        const int qa = q0 < SEQ ? q0 : SEQ - 1;
        const int qb = q1 < SEQ ? q1 : SEQ - 1;

        unsigned af[4][4];
#pragma unroll
        for (int kc = 0; kc < 4; kc++) {
            const float* pa = base + (size_t)qa * (3 * EMB) + kc * 8 + lq;
            const float* pc = base + (size_t)qb * (3 * EMB) + kc * 8 + lq;
            af[kc][0] = __float_as_uint(rtf32(pa[0] * scale));
            af[kc][1] = __float_as_uint(rtf32(pc[0] * scale));
            af[kc][2] = __float_as_uint(rtf32(pa[4] * scale));
            af[kc][3] = __float_as_uint(rtf32(pc[4] * scale));
        }

        float acc[26][4];
#pragma unroll
        for (int j = 0; j < 26; j++) {
            acc[j][0] = 0.f; acc[j][1] = 0.f; acc[j][2] = 0.f; acc[j][3] = 0.f;
        }
#pragma unroll
        for (int j = 0; j < 25; j++) {
            const float* kbp = Ks + (j * 8 + r) * KS_STRIDE + lq;
#pragma unroll
            for (int kc = 0; kc < 4; kc++) {
                unsigned b0 = __float_as_uint(kbp[kc * 8]);
                unsigned b1 = __float_as_uint(kbp[kc * 8 + 4]);
                mma_tf32(acc[j], af[kc], b0, b1);
            }
        }
        if (lq >= 2) {
            acc[24][0] = -1e30f; acc[24][1] = -1e30f;
            acc[24][2] = -1e30f; acc[24][3] = -1e30f;
        }
        acc[25][0] = -1e30f; acc[25][1] = -1e30f;
        acc[25][2] = -1e30f; acc[25][3] = -1e30f;

        float m0 = -1e30f, m1 = -1e30f;
#pragma unroll
        for (int j = 0; j < 26; j++) {
            m0 = fmaxf(m0, fmaxf(acc[j][0], acc[j][1]));
            m1 = fmaxf(m1, fmaxf(acc[j][2], acc[j][3]));
        }
        m0 = fmaxf(m0, __shfl_xor_sync(0xffffffffu, m0, 1));
        m0 = fmaxf(m0, __shfl_xor_sync(0xffffffffu, m0, 2));
        m1 = fmaxf(m1, __shfl_xor_sync(0xffffffffu, m1, 1));
        m1 = fmaxf(m1, __shfl_xor_sync(0xffffffffu, m1, 2));
        float l0 = 0.f, l1 = 0.f;
#pragma unroll
        for (int j = 0; j < 26; j++) {
            acc[j][0] = __expf(acc[j][0] - m0);
            acc[j][1] = __expf(acc[j][1] - m0);
            acc[j][2] = __expf(acc[j][2] - m1);
            acc[j][3] = __expf(acc[j][3] - m1);
            l0 += acc[j][0] + acc[j][1];
            l1 += acc[j][2] + acc[j][3];
        }
        l0 += __shfl_xor_sync(0xffffffffu, l0, 1);
        l0 += __shfl_xor_sync(0xffffffffu, l0, 2);
        l1 += __shfl_xor_sync(0xffffffffu, l1, 1);
        l1 += __shfl_xor_sync(0xffffffffu, l1, 2);
        const float inv0 = 1.f / l0;
        const float inv1 = 1.f / l1;

        float O[4][4];
#pragma unroll
        for (int nt = 0; nt < 4; nt++) {
            O[nt][0] = 0.f; O[nt][1] = 0.f; O[nt][2] = 0.f; O[nt][3] = 0.f;
        }
#pragma unroll
        for (int ch = 0; ch < 4; ch++) {
            const int njt = (ch < 3) ? 8 : 2;
#pragma unroll
            for (int jj = 0; jj < 8; jj++) {
                if (jj < njt) {
                    const int j = ch * 8 + jj;
                    float* p0 = Pw + r * PS_STRIDE + jj * 8 + 2 * lq;
                    float* p1 = Pw + (r + 8) * PS_STRIDE + jj * 8 + 2 * lq;
                    p0[0] = rtf32(acc[j][0]); p0[1] = rtf32(acc[j][1]);
                    p1[0] = rtf32(acc[j][2]); p1[1] = rtf32(acc[j][3]);
                }
            }
            __syncwarp();
            const int nkk = (ch < 3) ? 8 : 2;
#pragma unroll
            for (int kk = 0; kk < 8; kk++) {
                if (kk < nkk) {
                    unsigned pa[4];
                    pa[0] = __float_as_uint(Pw[r * PS_STRIDE + kk * 8 + lq]);
                    pa[1] = __float_as_uint(Pw[(r + 8) * PS_STRIDE + kk * 8 + lq]);
                    pa[2] = __float_as_uint(Pw[r * PS_STRIDE + kk * 8 + lq + 4]);
                    pa[3] = __float_as_uint(Pw[(r + 8) * PS_STRIDE + kk * 8 + lq + 4]);
                    const float* vbp = Vt + r * VT_STRIDE + ch * 64 + kk * 8 + lq;
#pragma unroll
                    for (int nt = 0; nt < 4; nt++) {
                        unsigned b0 = __float_as_uint(vbp[nt * 8 * VT_STRIDE]);
                        unsigned b1 = __float_as_uint(vbp[nt * 8 * VT_STRIDE + 4]);
                        mma_tf32(O[nt], pa, b0, b1);
                    }
                }
            }
            __syncwarp();
        }

        if (q0 < SEQ) {
            float* op = o + (size_t)(b * SEQ + q0) * EMB + hh * HDIM + 2 * lq;
#pragma unroll
            for (int nt = 0; nt < 4; nt++) {
                float2 v = make_float2(rtf32(O[nt][0] * inv0), rtf32(O[nt][1] * inv0));
                *(float2*)(op + nt * 8) = v;
            }
        }
        if (q1 < SEQ) {
            float* op = o + (size_t)(b * SEQ + q1) * EMB + hh * HDIM + 2 * lq;
#pragma unroll
            for (int nt = 0; nt < 4; nt++) {
                float2 v = make_float2(rtf32(O[nt][2] * inv1), rtf32(O[nt][3] * inv1));
                *(float2*)(op + nt * 8) = v;
            }
        }
    }
}
#define SMEM_ATTN_TC ((208*KS_STRIDE + 32*VT_STRIDE + 8*16*PS_STRIDE) * 4)

// ============================================================
// 7. Mean-pool + classifier
// ============================================================
__global__ void __launch_bounds__(256)
pool_cls_kernel(const float* __restrict__ h, const float* __restrict__ cw,
                const float* __restrict__ cb, float* __restrict__ out)
{
    int b = blockIdx.x;
    int e = threadIdx.x;
    const float* hp = h + (size_t)b * SEQ * EMB + e;
    float s = 0.f;
    for (int t = 0; t < SEQ; t++) s += hp[(size_t)t * EMB];
    __shared__ float sp[EMB];
    sp[e] = s * (1.f / 196.f);
    __syncthreads();
    if (e < NCLS) {
        float acc = cb[e];
        const float* w = cw + e * EMB;
        for (int k = 0; k < EMB; k++) acc += sp[k] * w[k];
        out[b * NCLS + e] = acc;
    }
}

// ============================================================
// launcher
// ============================================================
extern "C" void kernel_launch(void* const* d_in, const int* in_sizes, int n_in,
                              void* d_out, int out_size)
{
    const float* x    = (const float*)d_in[0];
    const float* qfw  = (const float*)d_in[1];
    const float* qfb  = (const float*)d_in[2];
    const float* pww  = (const float*)d_in[3];
    const float* pwb  = (const float*)d_in[4];
    const float* embw = (const float*)d_in[5];
    const float* embb = (const float*)d_in[6];
    const float* inw  = (const float*)d_in[7];
    const float* inb  = (const float*)d_in[8];
    const float* outw = (const float*)d_in[9];
    const float* outb = (const float*)d_in[10];
    const float* thet = (const float*)d_in[11];
    const float* l1w  = (const float*)d_in[12];
    const float* l1b  = (const float*)d_in[13];
    const float* l2w  = (const float*)d_in[14];
    const float* l2b  = (const float*)d_in[15];
    const float* ln1g = (const float*)d_in[16];
    const float* ln1b = (const float*)d_in[17];
    const float* ln2g = (const float*)d_in[18];
    const float* ln2b = (const float*)d_in[19];
    const float* clsw = (const float*)d_in[20];
    const float* clsb = (const float*)d_in[21];
    float* out = (float*)d_out;

    float *h, *qkv, *attn, *feat, *w_in, *w_out, *w_l2;
    cudaGetSymbolAddress((void**)&h,     g_h);
    cudaGetSymbolAddress((void**)&qkv,   g_qkv);
    cudaGetSymbolAddress((void**)&attn,  g_attn);
    cudaGetSymbolAddress((void**)&feat,  g_feat);
    cudaGetSymbolAddress((void**)&w_in,  g_w_in);
    cudaGetSymbolAddress((void**)&w_out, g_w_out);
    cudaGetSymbolAddress((void**)&w_l2,  g_w_l2);

    cudaFuncSetAttribute(attention_tc,
                         cudaFuncAttributeMaxDynamicSharedMemorySize, SMEM_ATTN_TC);
    cudaFuncSetAttribute(gemm256<0,0>,
                         cudaFuncAttributeMaxDynamicSharedMemorySize, SMEM_G256);
    cudaFuncSetAttribute(gemm256<0,1>,
                         cudaFuncAttributeMaxDynamicSharedMemorySize, SMEM_G256);
    cudaFuncSetAttribute(gemm256<1,1>,
                         cudaFuncAttributeMaxDynamicSharedMemorySize, SMEM_G256);

    const int n_in_w  = NBLK * 3 * EMB * EMB;
    const int n_out_w = NBLK * EMB * EMB;
    const int n_l2_w  = NBLK * EMB * FF;
    tf32_cvt_kernel<<<(n_in_w  + 255) / 256, 256>>>(inw,  w_in,  n_in_w);
    tf32_cvt_kernel<<<(n_out_w + 255) / 256, 256>>>(outw, w_out, n_out_w);
    tf32_cvt_kernel<<<(n_l2_w  + 255) / 256, 256>>>(l2w,  w_l2,  n_l2_w);

    quanv_kernel<<<(TOK * 4 + 255) / 256, 256>>>(x, qfw, qfb, pww, pwb, feat);
    embed_kernel<<<TOK, 256>>>(feat, embw, embb, h);

    for (int i = 0; i < NBLK; i++) {
        // QKV projection: [TOK,256] x [768,256]^T, plain bias epilogue
        gemm256<0,0><<<dim3(3, TOK / 128), 256, SMEM_G256>>>(
            h, w_in + (size_t)i * 3 * EMB * EMB, inb + (size_t)i * 3 * EMB,
            nullptr, nullptr, nullptr, nullptr, nullptr, nullptr,
            qkv, TOK, 3 * EMB, EMB);

        attention_tc<<<dim3(HEADS, BATCH), 256, SMEM_ATTN_TC>>>(qkv, attn);

        // out-proj + residual + LN1 fused, writes h in place
        gemm256<0,1><<<dim3(1, TOK / 128), 256, SMEM_G256>>>(
            attn, w_out + (size_t)i * EMB * EMB, outb + (size_t)i * EMB,
            h, ln1g + (size_t)i * EMB, ln1b + (size_t)i * EMB,
            nullptr, nullptr, nullptr,
            h, TOK, EMB, EMB);

        // quantum FFN l1 (A computed on the fly) + l2 GEMM + residual + LN2
        gemm256<1,1><<<dim3(1, TOK / 128), 256, SMEM_G256>>>(
            h, w_l2 + (size_t)i * EMB * FF, l2b + (size_t)i * EMB,
            h, ln2g + (size_t)i * EMB, ln2b + (size_t)i * EMB,
            l1w + (size_t)i * FF * NQBIT, l1b + (size_t)i * FF,
            thet + (size_t)i * NQBIT,
            h, TOK, EMB, FF);
    }

    pool_cls_kernel<<<BATCH, 256>>>(h, clsw, clsb, out);
}

// round 7
// speedup vs baseline: 3.8836x; 1.5384x over previous
#include <cuda_runtime.h>
#include <cuda_fp16.h>
#include <math.h>
#include <stdint.h>

// ---------------- problem constants ----------------
#define BATCH 256
#define SEQ   196
#define EMB   256
#define HEADS 8
#define HDIM  32
#define NBLK  4
#define FF    1024
#define NQBIT 8
#define NCLS  10
#define TOK   (BATCH*SEQ)          // 50176

// ---------------- device scratch ----------------
__device__ __half g_h[(size_t)TOK * EMB];
__device__ __half g_qkv[(size_t)TOK * 3 * EMB];
__device__ __half g_attn[(size_t)TOK * EMB];
__device__ float  g_feat[(size_t)TOK * 4];
__device__ float  g_pe[(size_t)SEQ * EMB];
__device__ __half g_w_in[(size_t)NBLK * 3 * EMB * EMB];
__device__ __half g_w_out[(size_t)NBLK * EMB * EMB];
__device__ __half g_w_l2[(size_t)NBLK * EMB * FF];

// ---------------- helpers ----------------
__device__ __forceinline__ void cp_async16(void* smem, const void* gmem) {
    unsigned s = (unsigned)__cvta_generic_to_shared(smem);
    asm volatile("cp.async.ca.shared.global [%0], [%1], 16;" :: "r"(s), "l"(gmem));
}
__device__ __forceinline__ void cp_commit() { asm volatile("cp.async.commit_group;"); }
template<int N> __device__ __forceinline__ void cp_wait() {
    asm volatile("cp.async.wait_group %0;" :: "n"(N));
}
__device__ __forceinline__ void mma_f16(float* c, const unsigned* a, unsigned b0, unsigned b1) {
    asm volatile(
        "mma.sync.aligned.m16n8k16.row.col.f32.f16.f16.f32 "
        "{%0,%1,%2,%3}, {%4,%5,%6,%7}, {%8,%9}, {%0,%1,%2,%3};"
        : "+f"(c[0]), "+f"(c[1]), "+f"(c[2]), "+f"(c[3])
        : "r"(a[0]), "r"(a[1]), "r"(a[2]), "r"(a[3]), "r"(b0), "r"(b1));
}
__device__ __forceinline__ unsigned ldu(const __half* p) {
    return *(const unsigned*)(const void*)p;
}
__device__ __forceinline__ unsigned h2u(__half2 v) {
    return *(unsigned*)&v;
}

// ============================================================
// 0. weight fp16 conversion + PE table pre-passes
// ============================================================
__global__ void h_cvt_kernel(const float* __restrict__ src, __half* __restrict__ dst, int n)
{
    int i = blockIdx.x * 256 + threadIdx.x;
    if (i < n) dst[i] = __float2half_rn(src[i]);
}
__global__ void pe_kernel(float* __restrict__ pe)
{
    int s = blockIdx.x, e = threadIdx.x;
    int p2 = e & ~1;
    float ang = (float)s * expf((float)p2 * (-9.210340371976184f / 256.0f));
    pe[s * EMB + e] = (e & 1) ? cosf(ang) : sinf(ang);
}

// ============================================================
// 1. Quanvolution
// ============================================================
__global__ void quanv_kernel(const float* __restrict__ x,
                             const float* __restrict__ qw,
                             const float* __restrict__ qb,
                             const float* __restrict__ pw,
                             const float* __restrict__ pb,
                             float* __restrict__ feat)
{
    int idx = blockIdx.x * 256 + threadIdx.x;
    if (idx >= TOK * 4) return;
    int c  = idx & 3;
    int s  = (idx >> 2) % SEQ;
    int b  = idx / (SEQ * 4);
    int flat = s * 4 + c;
    int ch = flat / SEQ;
    int sp = flat % SEQ;
    int i  = sp / 14, j = sp % 14;

    float acc = pb[ch];
#pragma unroll
    for (int c2 = 0; c2 < 4; c2++) {
        const float* xb = x + (((size_t)b * 4 + c2) * 28 + 2 * i) * 28 + 2 * j;
        float conv = qb[c2]
                   + xb[0]  * qw[c2 * 4 + 0]
                   + xb[1]  * qw[c2 * 4 + 1]
                   + xb[28] * qw[c2 * 4 + 2]
                   + xb[29] * qw[c2 * 4 + 3];
        acc += pw[ch * 4 + c2] * conv;
    }
    feat[idx] = acc;
}

// ============================================================
// 2. Embedding + PE — output fp16
// ============================================================
__global__ void embed_kernel(const float* __restrict__ feat,
                             const float* __restrict__ ew,
                             const float* __restrict__ eb,
                             const float* __restrict__ pe,
                             __half* __restrict__ h)
{
    int m = blockIdx.x;
    int e = threadIdx.x;
    float4 f = *(const float4*)(feat + (size_t)m * 4);
    float4 w = *(const float4*)(ew + (size_t)e * 4);
    float acc = eb[e] + f.x * w.x + f.y * w.y + f.z * w.z + f.w * w.w;
    acc += pe[(m % SEQ) * EMB + e];
    h[(size_t)m * EMB + e] = __float2half_rn(acc);
}

// ============================================================
// 3. fp16 tensor-core GEMM, CTA 128x256, 8 warps @ 64x64, K-chunk 32.
//    ASRC: 1 = A computed on the fly (quantum FFN l1), else cp.async.
//    EPI:  1 = bias + resid + LayerNorm (N==256, grid.x==1, in-place ok).
// ============================================================
#define GKH 40                               // halves per smem row
#define SA_BYTES (128*GKH*2)                 // 10240
#define SB_BYTES (256*GKH*2)                 // 20480
#define OFF_SRED  0                          // float2[128][4] = 4096 B
#define OFF_BIAS  4096
#define OFF_G     5120
#define OFF_BL    6144
#define OFF_QM    7168                       // float[128][8]
#define OFF_SL    11264                      // float[2][32][8]
#define OFF_SLB   13312                      // float[2][32]
#define OFF_SA    13568                      // 2 x SA_BYTES
#define OFF_SB    (OFF_SA + 2*SA_BYTES)      // 34048
#define SMEM_GH   (OFF_SB + 2*SB_BYTES)      // 75008 B

template<int ASRC, int EPI>
__global__ void __launch_bounds__(256, 1)
gemm_h(const __half* __restrict__ A, const __half* __restrict__ W,
       const float* __restrict__ bias, const __half* __restrict__ resid,
       const float* __restrict__ lng, const float* __restrict__ lnbb,
       const float* __restrict__ l1w, const float* __restrict__ l1b,
       const float* __restrict__ theta,
       __half* __restrict__ C, int M, int N, int K)
{
    extern __shared__ char smc[];
    float2* sred = (float2*)(smc + OFF_SRED);
    float*  sbias = (float*)(smc + OFF_BIAS);
    float*  sg    = (float*)(smc + OFF_G);
    float*  sbl   = (float*)(smc + OFF_BL);
    float*  qm    = (float*)(smc + OFF_QM);
    float*  sL    = (float*)(smc + OFF_SL);
    float*  slb   = (float*)(smc + OFF_SLB);
    __half* sA    = (__half*)(smc + OFF_SA);
    __half* sB    = (__half*)(smc + OFF_SB);

    const int tid  = threadIdx.x;
    const int lane = tid & 31;
    const int wid  = tid >> 5;
    const int bm   = blockIdx.y * 128;
    const int bn   = blockIdx.x * 256;
    const int wm   = (wid & 1) * 64;
    const int wn   = (wid >> 1) * 64;
    const int ln4  = lane >> 2;
    const int lnm  = lane & 3;

    sbias[tid] = bias[bn + tid];
    if (EPI == 1) { sg[tid] = lng[tid]; sbl[tid] = lnbb[tid]; }

    if (ASRC == 1) {
        if (tid < 128) {
            const __half* hp = A + (size_t)(bm + tid) * EMB;
#pragma unroll
            for (int q = 0; q < 8; q++)
                qm[tid * 8 + q] = cosf(__half2float(hp[q])) * cosf(theta[q]);
        }
        if (tid < 64) {
            int rr = tid >> 1, hf = (tid & 1) * 4;
            *(float4*)(sL + rr * 8 + hf) = *(const float4*)(l1w + rr * 8 + hf);
        }
        if (tid < 32) slb[tid] = l1b[tid];
    }

    float acc[4][8][4];
#pragma unroll
    for (int i = 0; i < 4; i++)
#pragma unroll
        for (int j = 0; j < 8; j++)
#pragma unroll
            for (int t = 0; t < 4; t++) acc[i][j][t] = 0.f;

    const int nc = K >> 5;
    const int ar = tid >> 1;          // staging row for A
    const int asg = (tid & 1) * 2;    // A 16B-segment pair

    // ---- prologue: chunk 0 ----
    {
        const __half* Wg = W + (size_t)(bn + tid) * K;
        char* bw = (char*)sB + tid * (GKH * 2);
#pragma unroll
        for (int q = 0; q < 4; q++) cp_async16(bw + q * 16, Wg + q * 8);
        if (ASRC == 0) {
            const __half* Ag = A + (size_t)(bm + ar) * K + asg * 8;
            char* aw = (char*)sA + ar * (GKH * 2) + asg * 16;
            cp_async16(aw, Ag);
            cp_async16(aw + 16, Ag + 8);
        }
        cp_commit();
    }
    if (ASRC == 1) {
        __syncthreads();     // qm, sL0, slb0 visible
        int m = tid >> 1, kb = (tid & 1) * 16;
        float qv[8];
        *(float4*)qv       = *(const float4*)(qm + m * 8);
        *(float4*)(qv + 4) = *(const float4*)(qm + m * 8 + 4);
        unsigned outp[8];
#pragma unroll
        for (int j2 = 0; j2 < 8; j2++) {
            float v01[2];
#pragma unroll
            for (int e = 0; e < 2; e++) {
                int kl = kb + j2 * 2 + e;
                const float* lr = sL + kl * 8;
                float v = slb[kl];
#pragma unroll
                for (int q = 0; q < 8; q++) v += qv[q] * lr[q];
                v01[e] = fmaxf(v, 0.f);
            }
            outp[j2] = h2u(__floats2half2_rn(v01[0], v01[1]));
        }
        char* aw = (char*)sA + m * (GKH * 2) + kb * 2;
        *(uint4*)aw        = make_uint4(outp[0], outp[1], outp[2], outp[3]);
        *(uint4*)(aw + 16) = make_uint4(outp[4], outp[5], outp[6], outp[7]);
    }

    // ---- main loop ----
    for (int c = 0; c < nc; c++) {
        const int buf = c & 1;
        const int nb  = buf ^ 1;
        if (c + 1 < nc) {
            const __half* Wg2 = W + (size_t)(bn + tid) * K + (c + 1) * 32;
            char* bw = (char*)sB + nb * SB_BYTES + tid * (GKH * 2);
#pragma unroll
            for (int q = 0; q < 4; q++) cp_async16(bw + q * 16, Wg2 + q * 8);
            if (ASRC == 0) {
                const __half* Ag2 = A + (size_t)(bm + ar) * K + (c + 1) * 32 + asg * 8;
                char* aw = (char*)sA + nb * SA_BYTES + ar * (GKH * 2) + asg * 16;
                cp_async16(aw, Ag2);
                cp_async16(aw + 16, Ag2 + 8);
            } else {
                if (tid < 64) {
                    int rr = tid >> 1, hf = (tid & 1) * 4;
                    *(float4*)(sL + ((c + 1) & 1) * 256 + rr * 8 + hf) =
                        *(const float4*)(l1w + ((size_t)(c + 1) * 32 + rr) * 8 + hf);
                }
                if (tid < 32) slb[((c + 1) & 1) * 32 + tid] = l1b[(c + 1) * 32 + tid];
            }
            cp_commit();
            cp_wait<1>();
        } else {
            cp_wait<0>();
        }
        __syncthreads();

        const __half* cA = sA + buf * (128 * GKH);
        const __half* cB = sB + buf * (256 * GKH);

#pragma unroll
        for (int s = 0; s < 2; s++) {
            const int k0 = s * 16;
            unsigned af[4][4];
#pragma unroll
            for (int i = 0; i < 4; i++) {
                const __half* p = cA + (wm + i * 16 + ln4) * GKH + k0 + 2 * lnm;
                af[i][0] = ldu(p);
                af[i][1] = ldu(p + 8 * GKH);
                af[i][2] = ldu(p + 8);
                af[i][3] = ldu(p + 8 * GKH + 8);
            }
#pragma unroll
            for (int j = 0; j < 8; j++) {
                const __half* pb = cB + (wn + j * 8 + ln4) * GKH + k0 + 2 * lnm;
                unsigned b0 = ldu(pb);
                unsigned b1 = ldu(pb + 8);
#pragma unroll
                for (int i = 0; i < 4; i++)
                    mma_f16(acc[i][j], af[i], b0, b1);
            }
        }

        if (ASRC == 1 && c + 1 < nc) {
            int m = tid >> 1, kb = (tid & 1) * 16;
            float qv[8];
            *(float4*)qv       = *(const float4*)(qm + m * 8);
            *(float4*)(qv + 4) = *(const float4*)(qm + m * 8 + 4);
            unsigned outp[8];
#pragma unroll
            for (int j2 = 0; j2 < 8; j2++) {
                float v01[2];
#pragma unroll
                for (int e = 0; e < 2; e++) {
                    int kl = kb + j2 * 2 + e;
                    const float* lr = sL + ((c + 1) & 1) * 256 + kl * 8;
                    float v = slb[((c + 1) & 1) * 32 + kl];
#pragma unroll
                    for (int q = 0; q < 8; q++) v += qv[q] * lr[q];
                    v01[e] = fmaxf(v, 0.f);
                }
                outp[j2] = h2u(__floats2half2_rn(v01[0], v01[1]));
            }
            char* aw = (char*)sA + nb * SA_BYTES + m * (GKH * 2) + kb * 2;
            *(uint4*)aw        = make_uint4(outp[0], outp[1], outp[2], outp[3]);
            *(uint4*)(aw + 16) = make_uint4(outp[4], outp[5], outp[6], outp[7]);
        }
        __syncthreads();
    }

    // ---- epilogue ----
    if (EPI == 0) {
#pragma unroll
        for (int i = 0; i < 4; i++) {
            const int gr0 = bm + wm + i * 16 + ln4;
#pragma unroll
            for (int j = 0; j < 8; j++) {
                const int col = wn + j * 8 + 2 * lnm;
                const float b0 = sbias[col], b1 = sbias[col + 1];
                *(__half2*)(C + (size_t)gr0 * N + bn + col) =
                    __floats2half2_rn(acc[i][j][0] + b0, acc[i][j][1] + b1);
                *(__half2*)(C + (size_t)(gr0 + 8) * N + bn + col) =
                    __floats2half2_rn(acc[i][j][2] + b0, acc[i][j][3] + b1);
            }
        }
    } else {
#pragma unroll
        for (int i = 0; i < 4; i++) {
            const int lr0 = wm + i * 16 + ln4;
            const int gr0 = bm + lr0;
            float s0 = 0.f, q0 = 0.f, s1 = 0.f, q1 = 0.f;
#pragma unroll
            for (int j = 0; j < 8; j++) {
                const int col = wn + j * 8 + 2 * lnm;
                const float b0 = sbias[col], b1 = sbias[col + 1];
                float2 r0 = __half22float2(*(const __half2*)(resid + (size_t)gr0 * 256 + col));
                float2 r1 = __half22float2(*(const __half2*)(resid + (size_t)(gr0 + 8) * 256 + col));
                float v0 = acc[i][j][0] + b0 + r0.x;
                float v1 = acc[i][j][1] + b1 + r0.y;
                float v2 = acc[i][j][2] + b0 + r1.x;
                float v3 = acc[i][j][3] + b1 + r1.y;
                acc[i][j][0] = v0; acc[i][j][1] = v1;
                acc[i][j][2] = v2; acc[i][j][3] = v3;
                s0 += v0 + v1; q0 += v0 * v0 + v1 * v1;
                s1 += v2 + v3; q1 += v2 * v2 + v3 * v3;
            }
#pragma unroll
            for (int o = 1; o <= 2; o <<= 1) {
                s0 += __shfl_xor_sync(0xffffffffu, s0, o);
                q0 += __shfl_xor_sync(0xffffffffu, q0, o);
                s1 += __shfl_xor_sync(0xffffffffu, s1, o);
                q1 += __shfl_xor_sync(0xffffffffu, q1, o);
            }
            if (lnm == 0) {
                sred[lr0 * 4 + (wid >> 1)]       = make_float2(s0, q0);
                sred[(lr0 + 8) * 4 + (wid >> 1)] = make_float2(s1, q1);
            }
        }
        __syncthreads();
#pragma unroll
        for (int i = 0; i < 4; i++) {
            const int lr0 = wm + i * 16 + ln4;
            const int gr0 = bm + lr0;
            float2 a0 = sred[lr0 * 4 + 0], a1 = sred[lr0 * 4 + 1];
            float2 a2 = sred[lr0 * 4 + 2], a3 = sred[lr0 * 4 + 3];
            float mean0 = (a0.x + a1.x + a2.x + a3.x) * (1.f / 256.f);
            float e0    = (a0.y + a1.y + a2.y + a3.y) * (1.f / 256.f);
            float rstd0 = rsqrtf(e0 - mean0 * mean0 + 1e-5f);
            float2 c0 = sred[(lr0 + 8) * 4 + 0], c1 = sred[(lr0 + 8) * 4 + 1];
            float2 c2 = sred[(lr0 + 8) * 4 + 2], c3 = sred[(lr0 + 8) * 4 + 3];
            float mean1 = (c0.x + c1.x + c2.x + c3.x) * (1.f / 256.f);
            float e1    = (c0.y + c1.y + c2.y + c3.y) * (1.f / 256.f);
            float rstd1 = rsqrtf(e1 - mean1 * mean1 + 1e-5f);
#pragma unroll
            for (int j = 0; j < 8; j++) {
                const int col = wn + j * 8 + 2 * lnm;
                const float g0 = sg[col], g1 = sg[col + 1];
                const float d0 = sbl[col], d1 = sbl[col + 1];
                *(__half2*)(C + (size_t)gr0 * 256 + col) = __floats2half2_rn(
                    (acc[i][j][0] - mean0) * rstd0 * g0 + d0,
                    (acc[i][j][1] - mean0) * rstd0 * g1 + d1);
                *(__half2*)(C + (size_t)(gr0 + 8) * 256 + col) = __floats2half2_rn(
                    (acc[i][j][2] - mean1) * rstd1 * g0 + d0,
                    (acc[i][j][3] - mean1) * rstd1 * g1 + d1);
            }
        }
    }
}

// ============================================================
// 4. fp16 tensor-core attention. One CTA per (head,batch), 8 warps.
// ============================================================
#define KS_ST 40
#define VT_ST 216
#define PS_ST 72

__global__ void __launch_bounds__(256, 1)
attention_h(const __half* __restrict__ qkv, __half* __restrict__ o)
{
    __shared__ __half Ks[208 * KS_ST];
    __shared__ __half Vt[32 * VT_ST];
    __shared__ __half Ps[8 * 16 * PS_ST];

    const int hh = blockIdx.x;
    const int b  = blockIdx.y;
    const int tid  = threadIdx.x;
    const int lane = tid & 31;
    const int wid  = tid >> 5;
    const int r    = lane >> 2;
    const int lq   = lane & 3;
    const float scale = 0.17677669529663687f;
    const __half* base = qkv + (size_t)b * SEQ * (3 * EMB) + hh * HDIM;

    // K: rows 0..207 (pad zero), 32 halves = 4 x 8-half segments
    for (int i = tid; i < 208 * 4; i += 256) {
        int s = i >> 2, sg = i & 3;
        float4 v = make_float4(0.f, 0.f, 0.f, 0.f);
        if (s < SEQ) v = *(const float4*)(base + (size_t)s * (3 * EMB) + EMB + sg * 8);
        *(float4*)(Ks + s * KS_ST + sg * 8) = v;
    }
    // V transposed: Vt[d][k]
    for (int i = tid; i < SEQ * 32; i += 256) {
        int s = i >> 5, d = i & 31;
        Vt[d * VT_ST + s] = base[(size_t)s * (3 * EMB) + 2 * EMB + d];
    }
    for (int i = tid; i < 32 * 20; i += 256) {   // pad keys 196..215
        int d = i / 20, c = SEQ + i % 20;
        Vt[d * VT_ST + c] = __float2half(0.f);
    }
    __syncthreads();

    __half* Pw = Ps + wid * 16 * PS_ST;

    for (int strip = wid; strip < 13; strip += 8) {
        const int q0 = strip * 16 + r;
        const int q1 = q0 + 8;
        const int qa = q0 < SEQ ? q0 : SEQ - 1;
        const int qb = q1 < SEQ ? q1 : SEQ - 1;

        // Q fragments (unscaled; scale applied inside exp)
        unsigned af[2][4];
#pragma unroll
        for (int kc = 0; kc < 2; kc++) {
            const __half* pa = base + (size_t)qa * (3 * EMB) + kc * 16 + 2 * lq;
            const __half* pc = base + (size_t)qb * (3 * EMB) + kc * 16 + 2 * lq;
            af[kc][0] = ldu(pa);
            af[kc][1] = ldu(pc);
            af[kc][2] = ldu(pa + 8);
            af[kc][3] = ldu(pc + 8);
        }

        // ---- scores ----
        float acc[26][4];
#pragma unroll
        for (int j = 0; j < 26; j++) {
            acc[j][0] = 0.f; acc[j][1] = 0.f; acc[j][2] = 0.f; acc[j][3] = 0.f;
        }
#pragma unroll
        for (int j = 0; j < 25; j++) {
            const __half* kbp = Ks + (j * 8 + r) * KS_ST + 2 * lq;
#pragma unroll
            for (int kc = 0; kc < 2; kc++) {
                unsigned b0 = ldu(kbp + kc * 16);
                unsigned b1 = ldu(kbp + kc * 16 + 8);
                mma_f16(acc[j], af[kc], b0, b1);
            }
        }
        if (lq >= 2) {
            acc[24][0] = -1e30f; acc[24][1] = -1e30f;
            acc[24][2] = -1e30f; acc[24][3] = -1e30f;
        }
        acc[25][0] = -1e30f; acc[25][1] = -1e30f;
        acc[25][2] = -1e30f; acc[25][3] = -1e30f;

        // ---- softmax (scale folded into exp) ----
        float m0 = -1e30f, m1 = -1e30f;
#pragma unroll
        for (int j = 0; j < 26; j++) {
            m0 = fmaxf(m0, fmaxf(acc[j][0], acc[j][1]));
            m1 = fmaxf(m1, fmaxf(acc[j][2], acc[j][3]));
        }
        m0 = fmaxf(m0, __shfl_xor_sync(0xffffffffu, m0, 1));
        m0 = fmaxf(m0, __shfl_xor_sync(0xffffffffu, m0, 2));
        m1 = fmaxf(m1, __shfl_xor_sync(0xffffffffu, m1, 1));
        m1 = fmaxf(m1, __shfl_xor_sync(0xffffffffu, m1, 2));
        float l0 = 0.f, l1 = 0.f;
#pragma unroll
        for (int j = 0; j < 26; j++) {
            acc[j][0] = __expf((acc[j][0] - m0) * scale);
            acc[j][1] = __expf((acc[j][1] - m0) * scale);
            acc[j][2] = __expf((acc[j][2] - m1) * scale);
            acc[j][3] = __expf((acc[j][3] - m1) * scale);
            l0 += acc[j][0] + acc[j][1];
            l1 += acc[j][2] + acc[j][3];
        }
        l0 += __shfl_xor_sync(0xffffffffu, l0, 1);
        l0 += __shfl_xor_sync(0xffffffffu, l0, 2);
        l1 += __shfl_xor_sync(0xffffffffu, l1, 1);
        l1 += __shfl_xor_sync(0xffffffffu, l1, 2);
        const float inv0 = 1.f / l0;
        const float inv1 = 1.f / l1;

        // ---- P @ V in chunks of 64 keys ----
        float O[4][4];
#pragma unroll
        for (int nt = 0; nt < 4; nt++) {
            O[nt][0] = 0.f; O[nt][1] = 0.f; O[nt][2] = 0.f; O[nt][3] = 0.f;
        }
#pragma unroll
        for (int ch = 0; ch < 4; ch++) {
            const int njt = (ch < 3) ? 8 : 2;
#pragma unroll
            for (int jj = 0; jj < 8; jj++) {
                if (jj < njt) {
                    const int j = ch * 8 + jj;
                    *(__half2*)(Pw + r * PS_ST + jj * 8 + 2 * lq) =
                        __floats2half2_rn(acc[j][0], acc[j][1]);
                    *(__half2*)(Pw + (r + 8) * PS_ST + jj * 8 + 2 * lq) =
                        __floats2half2_rn(acc[j][2], acc[j][3]);
                }
            }
            __syncwarp();
            const int nkk = (ch < 3) ? 4 : 1;
#pragma unroll
            for (int kk = 0; kk < 4; kk++) {
                if (kk < nkk) {
                    unsigned pa[4];
                    const __half* pp = Pw + r * PS_ST + kk * 16 + 2 * lq;
                    pa[0] = ldu(pp);
                    pa[1] = ldu(pp + 8 * PS_ST);
                    pa[2] = ldu(pp + 8);
                    pa[3] = ldu(pp + 8 * PS_ST + 8);
                    const __half* vbp = Vt + r * VT_ST + ch * 64 + kk * 16 + 2 * lq;
#pragma unroll
                    for (int nt = 0; nt < 4; nt++) {
                        unsigned b0 = ldu(vbp + nt * 8 * VT_ST);
                        unsigned b1 = ldu(vbp + nt * 8 * VT_ST + 8);
                        mma_f16(O[nt], pa, b0, b1);
                    }
                }
            }
            __syncwarp();
        }

        // ---- epilogue (fp16 out) ----
        if (q0 < SEQ) {
            __half* op = o + (size_t)(b * SEQ + q0) * EMB + hh * HDIM + 2 * lq;
#pragma unroll
            for (int nt = 0; nt < 4; nt++)
                *(__half2*)(op + nt * 8) =
                    __floats2half2_rn(O[nt][0] * inv0, O[nt][1] * inv0);
        }
        if (q1 < SEQ) {
            __half* op = o + (size_t)(b * SEQ + q1) * EMB + hh * HDIM + 2 * lq;
#pragma unroll
            for (int nt = 0; nt < 4; nt++)
                *(__half2*)(op + nt * 8) =
                    __floats2half2_rn(O[nt][2] * inv1, O[nt][3] * inv1);
        }
    }
}

// ============================================================
// 7. Mean-pool + classifier (h is fp16)
// ============================================================
__global__ void __launch_bounds__(256)
pool_cls_kernel(const __half* __restrict__ h, const float* __restrict__ cw,
                const float* __restrict__ cb, float* __restrict__ out)
{
    int b = blockIdx.x;
    int e = threadIdx.x;
    const __half* hp = h + (size_t)b * SEQ * EMB + e;
    float s = 0.f;
    for (int t = 0; t < SEQ; t++) s += __half2float(hp[(size_t)t * EMB]);
    __shared__ float sp[EMB];
    sp[e] = s * (1.f / 196.f);
    __syncthreads();
    if (e < NCLS) {
        float acc = cb[e];
        const float* w = cw + e * EMB;
        for (int k = 0; k < EMB; k++) acc += sp[k] * w[k];
        out[b * NCLS + e] = acc;
    }
}

// ============================================================
// launcher
// ============================================================
extern "C" void kernel_launch(void* const* d_in, const int* in_sizes, int n_in,
                              void* d_out, int out_size)
{
    const float* x    = (const float*)d_in[0];
    const float* qfw  = (const float*)d_in[1];
    const float* qfb  = (const float*)d_in[2];
    const float* pww  = (const float*)d_in[3];
    const float* pwb  = (const float*)d_in[4];
    const float* embw = (const float*)d_in[5];
    const float* embb = (const float*)d_in[6];
    const float* inw  = (const float*)d_in[7];
    const float* inb  = (const float*)d_in[8];
    const float* outw = (const float*)d_in[9];
    const float* outb = (const float*)d_in[10];
    const float* thet = (const float*)d_in[11];
    const float* l1w  = (const float*)d_in[12];
    const float* l1b  = (const float*)d_in[13];
    const float* l2w  = (const float*)d_in[14];
    const float* l2b  = (const float*)d_in[15];
    const float* ln1g = (const float*)d_in[16];
    const float* ln1b = (const float*)d_in[17];
    const float* ln2g = (const float*)d_in[18];
    const float* ln2b = (const float*)d_in[19];
    const float* clsw = (const float*)d_in[20];
    const float* clsb = (const float*)d_in[21];
    float* out = (float*)d_out;

    __half *h, *qkv, *attn, *w_in, *w_out, *w_l2;
    float *feat, *pe;
    cudaGetSymbolAddress((void**)&h,     g_h);
    cudaGetSymbolAddress((void**)&qkv,   g_qkv);
    cudaGetSymbolAddress((void**)&attn,  g_attn);
    cudaGetSymbolAddress((void**)&feat,  g_feat);
    cudaGetSymbolAddress((void**)&pe,    g_pe);
    cudaGetSymbolAddress((void**)&w_in,  g_w_in);
    cudaGetSymbolAddress((void**)&w_out, g_w_out);
    cudaGetSymbolAddress((void**)&w_l2,  g_w_l2);

    cudaFuncSetAttribute(gemm_h<0,0>,
                         cudaFuncAttributeMaxDynamicSharedMemorySize, SMEM_GH);
    cudaFuncSetAttribute(gemm_h<0,1>,
                         cudaFuncAttributeMaxDynamicSharedMemorySize, SMEM_GH);
    cudaFuncSetAttribute(gemm_h<1,1>,
                         cudaFuncAttributeMaxDynamicSharedMemorySize, SMEM_GH);

    const int n_in_w  = NBLK * 3 * EMB * EMB;
    const int n_out_w = NBLK * EMB * EMB;
    const int n_l2_w  = NBLK * EMB * FF;
    h_cvt_kernel<<<(n_in_w  + 255) / 256, 256>>>(inw,  w_in,  n_in_w);
    h_cvt_kernel<<<(n_out_w + 255) / 256, 256>>>(outw, w_out, n_out_w);
    h_cvt_kernel<<<(n_l2_w  + 255) / 256, 256>>>(l2w,  w_l2,  n_l2_w);
    pe_kernel<<<SEQ, EMB>>>(pe);

    quanv_kernel<<<(TOK * 4 + 255) / 256, 256>>>(x, qfw, qfb, pww, pwb, feat);
    embed_kernel<<<TOK, 256>>>(feat, embw, embb, pe, h);

    for (int i = 0; i < NBLK; i++) {
        // QKV projection
        gemm_h<0,0><<<dim3(3, TOK / 128), 256, SMEM_GH>>>(
            h, w_in + (size_t)i * 3 * EMB * EMB, inb + (size_t)i * 3 * EMB,
            nullptr, nullptr, nullptr, nullptr, nullptr, nullptr,
            qkv, TOK, 3 * EMB, EMB);

        attention_h<<<dim3(HEADS, BATCH), 256>>>(qkv, attn);

        // out-proj + residual + LN1, in place on h
        gemm_h<0,1><<<dim3(1, TOK / 128), 256, SMEM_GH>>>(
            attn, w_out + (size_t)i * EMB * EMB, outb + (size_t)i * EMB,
            h, ln1g + (size_t)i * EMB, ln1b + (size_t)i * EMB,
            nullptr, nullptr, nullptr,
            h, TOK, EMB, EMB);

        // quantum FFN l1 (in-kernel A) + l2 + residual + LN2, in place on h
        gemm_h<1,1><<<dim3(1, TOK / 128), 256, SMEM_GH>>>(
            h, w_l2 + (size_t)i * EMB * FF, l2b + (size_t)i * EMB,
            h, ln2g + (size_t)i * EMB, ln2b + (size_t)i * EMB,
            l1w + (size_t)i * FF * NQBIT, l1b + (size_t)i * FF,
            thet + (size_t)i * NQBIT,
            h, TOK, EMB, FF);
    }

    pool_cls_kernel<<<BATCH, 256>>>(h, clsw, clsb, out);
}

// round 8
// speedup vs baseline: 4.4371x; 1.1425x over previous
#include <cuda_runtime.h>
#include <cuda_fp16.h>
#include <math.h>
#include <stdint.h>

// ---------------- problem constants ----------------
#define BATCH 256
#define SEQ   196
#define EMB   256
#define HEADS 8
#define HDIM  32
#define NBLK  4
#define FF    1024
#define NQBIT 8
#define NCLS  10
#define TOK   (BATCH*SEQ)          // 50176

// ---------------- device scratch ----------------
__device__ __half g_h[(size_t)TOK * EMB];
__device__ __half g_qkv[(size_t)TOK * 3 * EMB];
__device__ __half g_attn[(size_t)TOK * EMB];
__device__ float  g_feat[(size_t)TOK * 4];
__device__ float  g_pe[(size_t)SEQ * EMB];
__device__ __half g_w_in[(size_t)NBLK * 3 * EMB * EMB];
__device__ __half g_w_out[(size_t)NBLK * EMB * EMB];
__device__ __half g_w_l2[(size_t)NBLK * EMB * FF];

// ---------------- helpers ----------------
__device__ __forceinline__ void cp_async16(void* smem, const void* gmem) {
    unsigned s = (unsigned)__cvta_generic_to_shared(smem);
    asm volatile("cp.async.ca.shared.global [%0], [%1], 16;" :: "r"(s), "l"(gmem));
}
__device__ __forceinline__ void cp_commit() { asm volatile("cp.async.commit_group;"); }
template<int N> __device__ __forceinline__ void cp_wait() {
    asm volatile("cp.async.wait_group %0;" :: "n"(N));
}
__device__ __forceinline__ void mma_f16(float* c, const unsigned* a, unsigned b0, unsigned b1) {
    asm volatile(
        "mma.sync.aligned.m16n8k16.row.col.f32.f16.f16.f32 "
        "{%0,%1,%2,%3}, {%4,%5,%6,%7}, {%8,%9}, {%0,%1,%2,%3};"
        : "+f"(c[0]), "+f"(c[1]), "+f"(c[2]), "+f"(c[3])
        : "r"(a[0]), "r"(a[1]), "r"(a[2]), "r"(a[3]), "r"(b0), "r"(b1));
}
__device__ __forceinline__ void ldmx4(unsigned& r0, unsigned& r1, unsigned& r2, unsigned& r3,
                                      unsigned addr) {
    asm volatile("ldmatrix.sync.aligned.m8n8.x4.shared.b16 {%0,%1,%2,%3}, [%4];"
        : "=r"(r0), "=r"(r1), "=r"(r2), "=r"(r3) : "r"(addr));
}
__device__ __forceinline__ unsigned ldu(const __half* p) {
    return *(const unsigned*)(const void*)p;
}
__device__ __forceinline__ unsigned h2u(__half2 v) {
    return *(unsigned*)&v;
}

// ============================================================
// 0. weight fp16 conversion + PE table pre-passes
// ============================================================
__global__ void h_cvt_kernel(const float* __restrict__ src, __half* __restrict__ dst, int n)
{
    int i = blockIdx.x * 256 + threadIdx.x;
    if (i < n) dst[i] = __float2half_rn(src[i]);
}
__global__ void pe_kernel(float* __restrict__ pe)
{
    int s = blockIdx.x, e = threadIdx.x;
    int p2 = e & ~1;
    float ang = (float)s * expf((float)p2 * (-9.210340371976184f / 256.0f));
    pe[s * EMB + e] = (e & 1) ? cosf(ang) : sinf(ang);
}

// ============================================================
// 1. Quanvolution
// ============================================================
__global__ void quanv_kernel(const float* __restrict__ x,
                             const float* __restrict__ qw,
                             const float* __restrict__ qb,
                             const float* __restrict__ pw,
                             const float* __restrict__ pb,
                             float* __restrict__ feat)
{
    int idx = blockIdx.x * 256 + threadIdx.x;
    if (idx >= TOK * 4) return;
    int c  = idx & 3;
    int s  = (idx >> 2) % SEQ;
    int b  = idx / (SEQ * 4);
    int flat = s * 4 + c;
    int ch = flat / SEQ;
    int sp = flat % SEQ;
    int i  = sp / 14, j = sp % 14;

    float acc = pb[ch];
#pragma unroll
    for (int c2 = 0; c2 < 4; c2++) {
        const float* xb = x + (((size_t)b * 4 + c2) * 28 + 2 * i) * 28 + 2 * j;
        float conv = qb[c2]
                   + xb[0]  * qw[c2 * 4 + 0]
                   + xb[1]  * qw[c2 * 4 + 1]
                   + xb[28] * qw[c2 * 4 + 2]
                   + xb[29] * qw[c2 * 4 + 3];
        acc += pw[ch * 4 + c2] * conv;
    }
    feat[idx] = acc;
}

// ============================================================
// 2. Embedding + PE — output fp16
// ============================================================
__global__ void embed_kernel(const float* __restrict__ feat,
                             const float* __restrict__ ew,
                             const float* __restrict__ eb,
                             const float* __restrict__ pe,
                             __half* __restrict__ h)
{
    int m = blockIdx.x;
    int e = threadIdx.x;
    float4 f = *(const float4*)(feat + (size_t)m * 4);
    float4 w = *(const float4*)(ew + (size_t)e * 4);
    float acc = eb[e] + f.x * w.x + f.y * w.y + f.z * w.z + f.w * w.w;
    acc += pe[(m % SEQ) * EMB + e];
    h[(size_t)m * EMB + e] = __float2half_rn(acc);
}

// ============================================================
// 3. fp16 tensor-core GEMM, CTA 128x256, 8 warps @ 64x64, K-chunk 64,
//    ldmatrix fragment loads.
//    ASRC: 1 = A computed on the fly (quantum FFN l1), else cp.async.
//    EPI:  1 = bias + resid + LayerNorm (N==256, grid.x==1, in-place ok).
// ============================================================
#define GKH 72                               // halves per smem row (64 + 8 pad)
#define SA_BYTES (128*GKH*2)                 // 18432
#define SB_BYTES (256*GKH*2)                 // 36864
#define OFF_SRED  0                          // float2[128][4] = 4096 B
#define OFF_BIAS  4096
#define OFF_G     5120
#define OFF_BL    6144
#define OFF_QM    7168                       // float[128][8] = 4096
#define OFF_SL    11264                      // float[2][64][8] = 4096
#define OFF_SLB   15360                      // float[2][64] = 512
#define OFF_SA    15872                      // 2 x SA_BYTES
#define OFF_SB    (OFF_SA + 2*SA_BYTES)      // 52736
#define SMEM_GH   (OFF_SB + 2*SB_BYTES)      // 126464 B

template<int ASRC>
__device__ __forceinline__ void stage_chunk(const __half* __restrict__ A,
                                            const __half* __restrict__ W,
                                            char* smc, int bm, int bn, int K,
                                            int cc, int buf, int tid)
{
    // B: 256 rows x 128 B; one thread per row, 8 x 16B
    const __half* Wg = W + (size_t)(bn + tid) * K + cc * 64;
    char* bw = smc + OFF_SB + buf * SB_BYTES + tid * (GKH * 2);
#pragma unroll
    for (int q = 0; q < 8; q++) cp_async16(bw + q * 16, Wg + q * 8);
    if (ASRC == 0) {
        // A: 128 rows x 128 B; two threads per row, 4 x 16B each
        int m = tid >> 1, hf = tid & 1;
        const __half* Ag = A + (size_t)(bm + m) * K + cc * 64 + hf * 32;
        char* aw = smc + OFF_SA + buf * SA_BYTES + m * (GKH * 2) + hf * 64;
#pragma unroll
        for (int q = 0; q < 4; q++) cp_async16(aw + q * 16, Ag + q * 8);
    }
}

__device__ __forceinline__ void compute_a_chunk64(char* smc, int buf, int slbuf, int tid)
{
    const float* qm  = (const float*)(smc + OFF_QM);
    const float* sL  = (const float*)(smc + OFF_SL);
    const float* slb = (const float*)(smc + OFF_SLB);
    int m = tid >> 1, kb = (tid & 1) * 32;
    float qv[8];
    *(float4*)qv       = *(const float4*)(qm + m * 8);
    *(float4*)(qv + 4) = *(const float4*)(qm + m * 8 + 4);
    unsigned outp[16];
#pragma unroll
    for (int j2 = 0; j2 < 16; j2++) {
        float v01[2];
#pragma unroll
        for (int e = 0; e < 2; e++) {
            int kl = kb + j2 * 2 + e;
            const float* lr = sL + slbuf * 512 + kl * 8;
            float v = slb[slbuf * 64 + kl];
#pragma unroll
            for (int q = 0; q < 8; q++) v += qv[q] * lr[q];
            v01[e] = fmaxf(v, 0.f);
        }
        outp[j2] = h2u(__floats2half2_rn(v01[0], v01[1]));
    }
    char* aw = smc + OFF_SA + buf * SA_BYTES + m * (GKH * 2) + kb * 2;
#pragma unroll
    for (int q4 = 0; q4 < 4; q4++)
        *(uint4*)(aw + q4 * 16) = make_uint4(outp[q4 * 4], outp[q4 * 4 + 1],
                                             outp[q4 * 4 + 2], outp[q4 * 4 + 3]);
}

template<int ASRC, int EPI>
__global__ void __launch_bounds__(256, 1)
gemm_h(const __half* __restrict__ A, const __half* __restrict__ W,
       const float* __restrict__ bias, const __half* __restrict__ resid,
       const float* __restrict__ lng, const float* __restrict__ lnbb,
       const float* __restrict__ l1w, const float* __restrict__ l1b,
       const float* __restrict__ theta,
       __half* __restrict__ C, int M, int N, int K)
{
    extern __shared__ char smc[];
    float2* sred  = (float2*)(smc + OFF_SRED);
    float*  sbias = (float*)(smc + OFF_BIAS);
    float*  sg    = (float*)(smc + OFF_G);
    float*  sbl   = (float*)(smc + OFF_BL);
    float*  qm    = (float*)(smc + OFF_QM);
    float*  sL    = (float*)(smc + OFF_SL);
    float*  slb   = (float*)(smc + OFF_SLB);

    const int tid  = threadIdx.x;
    const int lane = tid & 31;
    const int wid  = tid >> 5;
    const int bm   = blockIdx.y * 128;
    const int bn   = blockIdx.x * 256;
    const int wm   = (wid & 1) * 64;
    const int wn   = (wid >> 1) * 64;
    const int ln4  = lane >> 2;
    const int lnm  = lane & 3;
    const unsigned su = (unsigned)__cvta_generic_to_shared(smc);

    // ldmatrix lane-address components
    const int a_row = lane & 15;                 // rows 0..15 of the 16x16 A tile
    const int a_kq  = (lane >> 4) << 3;          // k-halves 0 / 8
    const int b_row = (lane & 7) + (((lane >> 4) & 1) << 3);  // j / j+1 rows
    const int b_kq  = ((lane >> 3) & 1) << 3;    // k-halves 0 / 8

    sbias[tid] = bias[bn + tid];
    if (EPI == 1) { sg[tid] = lng[tid]; sbl[tid] = lnbb[tid]; }

    if (ASRC == 1) {
        if (tid < 128) {
            const __half* hp = A + (size_t)(bm + tid) * EMB;
#pragma unroll
            for (int q = 0; q < 8; q++)
                qm[tid * 8 + q] = cosf(__half2float(hp[q])) * cosf(theta[q]);
        }
        if (tid < 128) {
            int rr = tid >> 1, hf = (tid & 1) * 4;
            *(float4*)(sL + rr * 8 + hf) = *(const float4*)(l1w + rr * 8 + hf);
        }
        if (tid < 64) slb[tid] = l1b[tid];
    }

    float acc[4][8][4];
#pragma unroll
    for (int i = 0; i < 4; i++)
#pragma unroll
        for (int j = 0; j < 8; j++)
#pragma unroll
            for (int t = 0; t < 4; t++) acc[i][j][t] = 0.f;

    const int nc = K >> 6;

    // ---- prologue: chunk 0 ----
    stage_chunk<ASRC>(A, W, smc, bm, bn, K, 0, 0, tid);
    cp_commit();
    if (ASRC == 1) {
        __syncthreads();     // qm, sL0, slb0 visible
        compute_a_chunk64(smc, 0, 0, tid);
    }

    // ---- main loop ----
    for (int c = 0; c < nc; c++) {
        const int buf = c & 1;
        const int nb  = buf ^ 1;
        if (c + 1 < nc) {
            stage_chunk<ASRC>(A, W, smc, bm, bn, K, c + 1, nb, tid);
            if (ASRC == 1) {
                if (tid < 128) {
                    int rr = tid >> 1, hf = (tid & 1) * 4;
                    *(float4*)(sL + ((c + 1) & 1) * 512 + rr * 8 + hf) =
                        *(const float4*)(l1w + ((size_t)(c + 1) * 64 + rr) * 8 + hf);
                }
                if (tid < 64) slb[((c + 1) & 1) * 64 + tid] = l1b[(c + 1) * 64 + tid];
            }
            cp_commit();
            cp_wait<1>();
        } else {
            cp_wait<0>();
        }
        __syncthreads();

        const unsigned abase = su + OFF_SA + buf * SA_BYTES;
        const unsigned bbase = su + OFF_SB + buf * SB_BYTES;

#pragma unroll
        for (int s = 0; s < 4; s++) {
            const int k0 = s * 16;
            unsigned af[4][4];
#pragma unroll
            for (int i = 0; i < 4; i++) {
                unsigned addr = abase +
                    ((wm + i * 16 + a_row) * GKH + k0 + a_kq) * 2;
                ldmx4(af[i][0], af[i][1], af[i][2], af[i][3], addr);
            }
#pragma unroll
            for (int j2 = 0; j2 < 4; j2++) {
                unsigned baddr = bbase +
                    ((wn + j2 * 16 + b_row) * GKH + k0 + b_kq) * 2;
                unsigned b0, b1, b2, b3;
                ldmx4(b0, b1, b2, b3, baddr);
#pragma unroll
                for (int i = 0; i < 4; i++) {
                    mma_f16(acc[i][2 * j2],     af[i], b0, b1);
                    mma_f16(acc[i][2 * j2 + 1], af[i], b2, b3);
                }
            }
        }

        if (ASRC == 1 && c + 1 < nc)
            compute_a_chunk64(smc, nb, (c + 1) & 1, tid);
        __syncthreads();
    }

    // ---- epilogue ----
    if (EPI == 0) {
#pragma unroll
        for (int i = 0; i < 4; i++) {
            const int gr0 = bm + wm + i * 16 + ln4;
#pragma unroll
            for (int j = 0; j < 8; j++) {
                const int col = wn + j * 8 + 2 * lnm;
                const float b0 = sbias[col], b1 = sbias[col + 1];
                *(__half2*)(C + (size_t)gr0 * N + bn + col) =
                    __floats2half2_rn(acc[i][j][0] + b0, acc[i][j][1] + b1);
                *(__half2*)(C + (size_t)(gr0 + 8) * N + bn + col) =
                    __floats2half2_rn(acc[i][j][2] + b0, acc[i][j][3] + b1);
            }
        }
    } else {
#pragma unroll
        for (int i = 0; i < 4; i++) {
            const int lr0 = wm + i * 16 + ln4;
            const int gr0 = bm + lr0;
            float s0 = 0.f, q0 = 0.f, s1 = 0.f, q1 = 0.f;
#pragma unroll
            for (int j = 0; j < 8; j++) {
                const int col = wn + j * 8 + 2 * lnm;
                const float b0 = sbias[col], b1 = sbias[col + 1];
                float2 r0 = __half22float2(*(const __half2*)(resid + (size_t)gr0 * 256 + col));
                float2 r1 = __half22float2(*(const __half2*)(resid + (size_t)(gr0 + 8) * 256 + col));
                float v0 = acc[i][j][0] + b0 + r0.x;
                float v1 = acc[i][j][1] + b1 + r0.y;
                float v2 = acc[i][j][2] + b0 + r1.x;
                float v3 = acc[i][j][3] + b1 + r1.y;
                acc[i][j][0] = v0; acc[i][j][1] = v1;
                acc[i][j][2] = v2; acc[i][j][3] = v3;
                s0 += v0 + v1; q0 += v0 * v0 + v1 * v1;
                s1 += v2 + v3; q1 += v2 * v2 + v3 * v3;
            }
#pragma unroll
            for (int o = 1; o <= 2; o <<= 1) {
                s0 += __shfl_xor_sync(0xffffffffu, s0, o);
                q0 += __shfl_xor_sync(0xffffffffu, q0, o);
                s1 += __shfl_xor_sync(0xffffffffu, s1, o);
                q1 += __shfl_xor_sync(0xffffffffu, q1, o);
            }
            if (lnm == 0) {
                sred[lr0 * 4 + (wid >> 1)]       = make_float2(s0, q0);
                sred[(lr0 + 8) * 4 + (wid >> 1)] = make_float2(s1, q1);
            }
        }
        __syncthreads();
#pragma unroll
        for (int i = 0; i < 4; i++) {
            const int lr0 = wm + i * 16 + ln4;
            const int gr0 = bm + lr0;
            float2 a0 = sred[lr0 * 4 + 0], a1 = sred[lr0 * 4 + 1];
            float2 a2 = sred[lr0 * 4 + 2], a3 = sred[lr0 * 4 + 3];
            float mean0 = (a0.x + a1.x + a2.x + a3.x) * (1.f / 256.f);
            float e0    = (a0.y + a1.y + a2.y + a3.y) * (1.f / 256.f);
            float rstd0 = rsqrtf(e0 - mean0 * mean0 + 1e-5f);
            float2 c0 = sred[(lr0 + 8) * 4 + 0], c1 = sred[(lr0 + 8) * 4 + 1];
            float2 c2 = sred[(lr0 + 8) * 4 + 2], c3 = sred[(lr0 + 8) * 4 + 3];
            float mean1 = (c0.x + c1.x + c2.x + c3.x) * (1.f / 256.f);
            float e1    = (c0.y + c1.y + c2.y + c3.y) * (1.f / 256.f);
            float rstd1 = rsqrtf(e1 - mean1 * mean1 + 1e-5f);
#pragma unroll
            for (int j = 0; j < 8; j++) {
                const int col = wn + j * 8 + 2 * lnm;
                const float g0 = sg[col], g1 = sg[col + 1];
                const float d0 = sbl[col], d1 = sbl[col + 1];
                *(__half2*)(C + (size_t)gr0 * 256 + col) = __floats2half2_rn(
                    (acc[i][j][0] - mean0) * rstd0 * g0 + d0,
                    (acc[i][j][1] - mean0) * rstd0 * g1 + d1);
                *(__half2*)(C + (size_t)(gr0 + 8) * 256 + col) = __floats2half2_rn(
                    (acc[i][j][2] - mean1) * rstd1 * g0 + d0,
                    (acc[i][j][3] - mean1) * rstd1 * g1 + d1);
            }
        }
    }
}

// ============================================================
// 4. fp16 tensor-core attention (unchanged from R7, known-good)
// ============================================================
#define KS_ST 40
#define VT_ST 216
#define PS_ST 72

__global__ void __launch_bounds__(256, 1)
attention_h(const __half* __restrict__ qkv, __half* __restrict__ o)
{
    __shared__ __half Ks[208 * KS_ST];
    __shared__ __half Vt[32 * VT_ST];
    __shared__ __half Ps[8 * 16 * PS_ST];

    const int hh = blockIdx.x;
    const int b  = blockIdx.y;
    const int tid  = threadIdx.x;
    const int lane = tid & 31;
    const int wid  = tid >> 5;
    const int r    = lane >> 2;
    const int lq   = lane & 3;
    const float scale = 0.17677669529663687f;
    const __half* base = qkv + (size_t)b * SEQ * (3 * EMB) + hh * HDIM;

    for (int i = tid; i < 208 * 4; i += 256) {
        int s = i >> 2, sg = i & 3;
        float4 v = make_float4(0.f, 0.f, 0.f, 0.f);
        if (s < SEQ) v = *(const float4*)(base + (size_t)s * (3 * EMB) + EMB + sg * 8);
        *(float4*)(Ks + s * KS_ST + sg * 8) = v;
    }
    for (int i = tid; i < SEQ * 32; i += 256) {
        int s = i >> 5, d = i & 31;
        Vt[d * VT_ST + s] = base[(size_t)s * (3 * EMB) + 2 * EMB + d];
    }
    for (int i = tid; i < 32 * 20; i += 256) {
        int d = i / 20, c = SEQ + i % 20;
        Vt[d * VT_ST + c] = __float2half(0.f);
    }
    __syncthreads();

    __half* Pw = Ps + wid * 16 * PS_ST;

    for (int strip = wid; strip < 13; strip += 8) {
        const int q0 = strip * 16 + r;
        const int q1 = q0 + 8;
        const int qa = q0 < SEQ ? q0 : SEQ - 1;
        const int qb = q1 < SEQ ? q1 : SEQ - 1;

        unsigned af[2][4];
#pragma unroll
        for (int kc = 0; kc < 2; kc++) {
            const __half* pa = base + (size_t)qa * (3 * EMB) + kc * 16 + 2 * lq;
            const __half* pc = base + (size_t)qb * (3 * EMB) + kc * 16 + 2 * lq;
            af[kc][0] = ldu(pa);
            af[kc][1] = ldu(pc);
            af[kc][2] = ldu(pa + 8);
            af[kc][3] = ldu(pc + 8);
        }

        float acc[26][4];
#pragma unroll
        for (int j = 0; j < 26; j++) {
            acc[j][0] = 0.f; acc[j][1] = 0.f; acc[j][2] = 0.f; acc[j][3] = 0.f;
        }
#pragma unroll
        for (int j = 0; j < 25; j++) {
            const __half* kbp = Ks + (j * 8 + r) * KS_ST + 2 * lq;
#pragma unroll
            for (int kc = 0; kc < 2; kc++) {
                unsigned b0 = ldu(kbp + kc * 16);
                unsigned b1 = ldu(kbp + kc * 16 + 8);
                mma_f16(acc[j], af[kc], b0, b1);
            }
        }
        if (lq >= 2) {
            acc[24][0] = -1e30f; acc[24][1] = -1e30f;
            acc[24][2] = -1e30f; acc[24][3] = -1e30f;
        }
        acc[25][0] = -1e30f; acc[25][1] = -1e30f;
        acc[25][2] = -1e30f; acc[25][3] = -1e30f;

        float m0 = -1e30f, m1 = -1e30f;
#pragma unroll
        for (int j = 0; j < 26; j++) {
            m0 = fmaxf(m0, fmaxf(acc[j][0], acc[j][1]));
            m1 = fmaxf(m1, fmaxf(acc[j][2], acc[j][3]));
        }
        m0 = fmaxf(m0, __shfl_xor_sync(0xffffffffu, m0, 1));
        m0 = fmaxf(m0, __shfl_xor_sync(0xffffffffu, m0, 2));
        m1 = fmaxf(m1, __shfl_xor_sync(0xffffffffu, m1, 1));
        m1 = fmaxf(m1, __shfl_xor_sync(0xffffffffu, m1, 2));
        float l0 = 0.f, l1 = 0.f;
#pragma unroll
        for (int j = 0; j < 26; j++) {
            acc[j][0] = __expf((acc[j][0] - m0) * scale);
            acc[j][1] = __expf((acc[j][1] - m0) * scale);
            acc[j][2] = __expf((acc[j][2] - m1) * scale);
            acc[j][3] = __expf((acc[j][3] - m1) * scale);
            l0 += acc[j][0] + acc[j][1];
            l1 += acc[j][2] + acc[j][3];
        }
        l0 += __shfl_xor_sync(0xffffffffu, l0, 1);
        l0 += __shfl_xor_sync(0xffffffffu, l0, 2);
        l1 += __shfl_xor_sync(0xffffffffu, l1, 1);
        l1 += __shfl_xor_sync(0xffffffffu, l1, 2);
        const float inv0 = 1.f / l0;
        const float inv1 = 1.f / l1;

        float O[4][4];
#pragma unroll
        for (int nt = 0; nt < 4; nt++) {
            O[nt][0] = 0.f; O[nt][1] = 0.f; O[nt][2] = 0.f; O[nt][3] = 0.f;
        }
#pragma unroll
        for (int ch = 0; ch < 4; ch++) {
            const int njt = (ch < 3) ? 8 : 2;
#pragma unroll
            for (int jj = 0; jj < 8; jj++) {
                if (jj < njt) {
                    const int j = ch * 8 + jj;
                    *(__half2*)(Pw + r * PS_ST + jj * 8 + 2 * lq) =
                        __floats2half2_rn(acc[j][0], acc[j][1]);
                    *(__half2*)(Pw + (r + 8) * PS_ST + jj * 8 + 2 * lq) =
                        __floats2half2_rn(acc[j][2], acc[j][3]);
                }
            }
            __syncwarp();
            const int nkk = (ch < 3) ? 4 : 1;
#pragma unroll
            for (int kk = 0; kk < 4; kk++) {
                if (kk < nkk) {
                    unsigned pa[4];
                    const __half* pp = Pw + r * PS_ST + kk * 16 + 2 * lq;
                    pa[0] = ldu(pp);
                    pa[1] = ldu(pp + 8 * PS_ST);
                    pa[2] = ldu(pp + 8);
                    pa[3] = ldu(pp + 8 * PS_ST + 8);
                    const __half* vbp = Vt + r * VT_ST + ch * 64 + kk * 16 + 2 * lq;
#pragma unroll
                    for (int nt = 0; nt < 4; nt++) {
                        unsigned b0 = ldu(vbp + nt * 8 * VT_ST);
                        unsigned b1 = ldu(vbp + nt * 8 * VT_ST + 8);
                        mma_f16(O[nt], pa, b0, b1);
                    }
                }
            }
            __syncwarp();
        }

        if (q0 < SEQ) {
            __half* op = o + (size_t)(b * SEQ + q0) * EMB + hh * HDIM + 2 * lq;
#pragma unroll
            for (int nt = 0; nt < 4; nt++)
                *(__half2*)(op + nt * 8) =
                    __floats2half2_rn(O[nt][0] * inv0, O[nt][1] * inv0);
        }
        if (q1 < SEQ) {
            __half* op = o + (size_t)(b * SEQ + q1) * EMB + hh * HDIM + 2 * lq;
#pragma unroll
            for (int nt = 0; nt < 4; nt++)
                *(__half2*)(op + nt * 8) =
                    __floats2half2_rn(O[nt][2] * inv1, O[nt][3] * inv1);
        }
    }
}

// ============================================================
// 7. Mean-pool + classifier (h is fp16)
// ============================================================
__global__ void __launch_bounds__(256)
pool_cls_kernel(const __half* __restrict__ h, const float* __restrict__ cw,
                const float* __restrict__ cb, float* __restrict__ out)
{
    int b = blockIdx.x;
    int e = threadIdx.x;
    const __half* hp = h + (size_t)b * SEQ * EMB + e;
    float s = 0.f;
    for (int t = 0; t < SEQ; t++) s += __half2float(hp[(size_t)t * EMB]);
    __shared__ float sp[EMB];
    sp[e] = s * (1.f / 196.f);
    __syncthreads();
    if (e < NCLS) {
        float acc = cb[e];
        const float* w = cw + e * EMB;
        for (int k = 0; k < EMB; k++) acc += sp[k] * w[k];
        out[b * NCLS + e] = acc;
    }
}

// ============================================================
// launcher
// ============================================================
extern "C" void kernel_launch(void* const* d_in, const int* in_sizes, int n_in,
                              void* d_out, int out_size)
{
    const float* x    = (const float*)d_in[0];
    const float* qfw  = (const float*)d_in[1];
    const float* qfb  = (const float*)d_in[2];
    const float* pww  = (const float*)d_in[3];
    const float* pwb  = (const float*)d_in[4];
    const float* embw = (const float*)d_in[5];
    const float* embb = (const float*)d_in[6];
    const float* inw  = (const float*)d_in[7];
    const float* inb  = (const float*)d_in[8];
    const float* outw = (const float*)d_in[9];
    const float* outb = (const float*)d_in[10];
    const float* thet = (const float*)d_in[11];
    const float* l1w  = (const float*)d_in[12];
    const float* l1b  = (const float*)d_in[13];
    const float* l2w  = (const float*)d_in[14];
    const float* l2b  = (const float*)d_in[15];
    const float* ln1g = (const float*)d_in[16];
    const float* ln1b = (const float*)d_in[17];
    const float* ln2g = (const float*)d_in[18];
    const float* ln2b = (const float*)d_in[19];
    const float* clsw = (const float*)d_in[20];
    const float* clsb = (const float*)d_in[21];
    float* out = (float*)d_out;

    __half *h, *qkv, *attn, *w_in, *w_out, *w_l2;
    float *feat, *pe;
    cudaGetSymbolAddress((void**)&h,     g_h);
    cudaGetSymbolAddress((void**)&qkv,   g_qkv);
    cudaGetSymbolAddress((void**)&attn,  g_attn);
    cudaGetSymbolAddress((void**)&feat,  g_feat);
    cudaGetSymbolAddress((void**)&pe,    g_pe);
    cudaGetSymbolAddress((void**)&w_in,  g_w_in);
    cudaGetSymbolAddress((void**)&w_out, g_w_out);
    cudaGetSymbolAddress((void**)&w_l2,  g_w_l2);

    cudaFuncSetAttribute(gemm_h<0,0>,
                         cudaFuncAttributeMaxDynamicSharedMemorySize, SMEM_GH);
    cudaFuncSetAttribute(gemm_h<0,1>,
                         cudaFuncAttributeMaxDynamicSharedMemorySize, SMEM_GH);
    cudaFuncSetAttribute(gemm_h<1,1>,
                         cudaFuncAttributeMaxDynamicSharedMemorySize, SMEM_GH);

    const int n_in_w  = NBLK * 3 * EMB * EMB;
    const int n_out_w = NBLK * EMB * EMB;
    const int n_l2_w  = NBLK * EMB * FF;
    h_cvt_kernel<<<(n_in_w  + 255) / 256, 256>>>(inw,  w_in,  n_in_w);
    h_cvt_kernel<<<(n_out_w + 255) / 256, 256>>>(outw, w_out, n_out_w);
    h_cvt_kernel<<<(n_l2_w  + 255) / 256, 256>>>(l2w,  w_l2,  n_l2_w);
    pe_kernel<<<SEQ, EMB>>>(pe);

    quanv_kernel<<<(TOK * 4 + 255) / 256, 256>>>(x, qfw, qfb, pww, pwb, feat);
    embed_kernel<<<TOK, 256>>>(feat, embw, embb, pe, h);

    for (int i = 0; i < NBLK; i++) {
        // QKV projection
        gemm_h<0,0><<<dim3(3, TOK / 128), 256, SMEM_GH>>>(
            h, w_in + (size_t)i * 3 * EMB * EMB, inb + (size_t)i * 3 * EMB,
            nullptr, nullptr, nullptr, nullptr, nullptr, nullptr,
            qkv, TOK, 3 * EMB, EMB);

        attention_h<<<dim3(HEADS, BATCH), 256>>>(qkv, attn);

        // out-proj + residual + LN1, in place on h
        gemm_h<0,1><<<dim3(1, TOK / 128), 256, SMEM_GH>>>(
            attn, w_out + (size_t)i * EMB * EMB, outb + (size_t)i * EMB,
            h, ln1g + (size_t)i * EMB, ln1b + (size_t)i * EMB,
            nullptr, nullptr, nullptr,
            h, TOK, EMB, EMB);

        // quantum FFN l1 (in-kernel A) + l2 + residual + LN2, in place on h
        gemm_h<1,1><<<dim3(1, TOK / 128), 256, SMEM_GH>>>(
            h, w_l2 + (size_t)i * EMB * FF, l2b + (size_t)i * EMB,
            h, ln2g + (size_t)i * EMB, ln2b + (size_t)i * EMB,
            l1w + (size_t)i * FF * NQBIT, l1b + (size_t)i * FF,
            thet + (size_t)i * NQBIT,
            h, TOK, EMB, FF);
    }

    pool_cls_kernel<<<BATCH, 256>>>(h, clsw, clsb, out);
}

// round 9
// speedup vs baseline: 4.4890x; 1.0117x over previous
#include <cuda_runtime.h>
#include <cuda_fp16.h>
#include <math.h>
#include <stdint.h>

// ---------------- problem constants ----------------
#define BATCH 256
#define SEQ   196
#define EMB   256
#define HEADS 8
#define HDIM  32
#define NBLK  4
#define FF    1024
#define NQBIT 8
#define NCLS  10
#define TOK   (BATCH*SEQ)          // 50176

// ---------------- device scratch ----------------
__device__ __half g_h[(size_t)TOK * EMB];
__device__ __half g_qkv[(size_t)TOK * 3 * EMB];
__device__ __half g_attn[(size_t)TOK * EMB];
__device__ float  g_feat[(size_t)TOK * 4];
__device__ float  g_pe[(size_t)SEQ * EMB];
__device__ __half g_w_in[(size_t)NBLK * 3 * EMB * EMB];
__device__ __half g_w_out[(size_t)NBLK * EMB * EMB];
__device__ __half g_w_l2[(size_t)NBLK * EMB * FF];

// ---------------- helpers ----------------
__device__ __forceinline__ void cp_async16(void* smem, const void* gmem) {
    unsigned s = (unsigned)__cvta_generic_to_shared(smem);
    asm volatile("cp.async.ca.shared.global [%0], [%1], 16;" :: "r"(s), "l"(gmem));
}
__device__ __forceinline__ void cp_commit() { asm volatile("cp.async.commit_group;"); }
template<int N> __device__ __forceinline__ void cp_wait() {
    asm volatile("cp.async.wait_group %0;" :: "n"(N));
}
__device__ __forceinline__ void mma_f16(float* c, const unsigned* a, unsigned b0, unsigned b1) {
    asm volatile(
        "mma.sync.aligned.m16n8k16.row.col.f32.f16.f16.f32 "
        "{%0,%1,%2,%3}, {%4,%5,%6,%7}, {%8,%9}, {%0,%1,%2,%3};"
        : "+f"(c[0]), "+f"(c[1]), "+f"(c[2]), "+f"(c[3])
        : "r"(a[0]), "r"(a[1]), "r"(a[2]), "r"(a[3]), "r"(b0), "r"(b1));
}
__device__ __forceinline__ void ldmx4(unsigned& r0, unsigned& r1, unsigned& r2, unsigned& r3,
                                      unsigned addr) {
    asm volatile("ldmatrix.sync.aligned.m8n8.x4.shared.b16 {%0,%1,%2,%3}, [%4];"
        : "=r"(r0), "=r"(r1), "=r"(r2), "=r"(r3) : "r"(addr));
}
__device__ __forceinline__ unsigned ldu(const __half* p) {
    return *(const unsigned*)(const void*)p;
}
__device__ __forceinline__ unsigned h2u(__half2 v) {
    return *(unsigned*)&v;
}

// ============================================================
// 0. weight fp16 conversion + PE table pre-passes
// ============================================================
__global__ void h_cvt_kernel(const float* __restrict__ src, __half* __restrict__ dst, int n)
{
    int i = blockIdx.x * 256 + threadIdx.x;
    if (i < n) dst[i] = __float2half_rn(src[i]);
}
__global__ void pe_kernel(float* __restrict__ pe)
{
    int s = blockIdx.x, e = threadIdx.x;
    int p2 = e & ~1;
    float ang = (float)s * expf((float)p2 * (-9.210340371976184f / 256.0f));
    pe[s * EMB + e] = (e & 1) ? cosf(ang) : sinf(ang);
}

// ============================================================
// 1. Quanvolution
// ============================================================
__global__ void quanv_kernel(const float* __restrict__ x,
                             const float* __restrict__ qw,
                             const float* __restrict__ qb,
                             const float* __restrict__ pw,
                             const float* __restrict__ pb,
                             float* __restrict__ feat)
{
    int idx = blockIdx.x * 256 + threadIdx.x;
    if (idx >= TOK * 4) return;
    int c  = idx & 3;
    int s  = (idx >> 2) % SEQ;
    int b  = idx / (SEQ * 4);
    int flat = s * 4 + c;
    int ch = flat / SEQ;
    int sp = flat % SEQ;
    int i  = sp / 14, j = sp % 14;

    float acc = pb[ch];
#pragma unroll
    for (int c2 = 0; c2 < 4; c2++) {
        const float* xb = x + (((size_t)b * 4 + c2) * 28 + 2 * i) * 28 + 2 * j;
        float conv = qb[c2]
                   + xb[0]  * qw[c2 * 4 + 0]
                   + xb[1]  * qw[c2 * 4 + 1]
                   + xb[28] * qw[c2 * 4 + 2]
                   + xb[29] * qw[c2 * 4 + 3];
        acc += pw[ch * 4 + c2] * conv;
    }
    feat[idx] = acc;
}

// ============================================================
// 2. Embedding + PE — output fp16
// ============================================================
__global__ void embed_kernel(const float* __restrict__ feat,
                             const float* __restrict__ ew,
                             const float* __restrict__ eb,
                             const float* __restrict__ pe,
                             __half* __restrict__ h)
{
    int m = blockIdx.x;
    int e = threadIdx.x;
    float4 f = *(const float4*)(feat + (size_t)m * 4);
    float4 w = *(const float4*)(ew + (size_t)e * 4);
    float acc = eb[e] + f.x * w.x + f.y * w.y + f.z * w.z + f.w * w.w;
    acc += pe[(m % SEQ) * EMB + e];
    h[(size_t)m * EMB + e] = __float2half_rn(acc);
}

// ============================================================
// 3. fp16 tensor-core GEMM, CTA 128x256, 8 warps @ 64x64, K-chunk 64,
//    ldmatrix fragment loads.  (unchanged from R8, known-good)
// ============================================================
#define GKH 72                               // halves per smem row (64 + 8 pad)
#define SA_BYTES (128*GKH*2)                 // 18432
#define SB_BYTES (256*GKH*2)                 // 36864
#define OFF_SRED  0                          // float2[128][4] = 4096 B
#define OFF_BIAS  4096
#define OFF_G     5120
#define OFF_BL    6144
#define OFF_QM    7168                       // float[128][8] = 4096
#define OFF_SL    11264                      // float[2][64][8] = 4096
#define OFF_SLB   15360                      // float[2][64] = 512
#define OFF_SA    15872                      // 2 x SA_BYTES
#define OFF_SB    (OFF_SA + 2*SA_BYTES)      // 52736
#define SMEM_GH   (OFF_SB + 2*SB_BYTES)      // 126464 B

template<int ASRC>
__device__ __forceinline__ void stage_chunk(const __half* __restrict__ A,
                                            const __half* __restrict__ W,
                                            char* smc, int bm, int bn, int K,
                                            int cc, int buf, int tid)
{
    const __half* Wg = W + (size_t)(bn + tid) * K + cc * 64;
    char* bw = smc + OFF_SB + buf * SB_BYTES + tid * (GKH * 2);
#pragma unroll
    for (int q = 0; q < 8; q++) cp_async16(bw + q * 16, Wg + q * 8);
    if (ASRC == 0) {
        int m = tid >> 1, hf = tid & 1;
        const __half* Ag = A + (size_t)(bm + m) * K + cc * 64 + hf * 32;
        char* aw = smc + OFF_SA + buf * SA_BYTES + m * (GKH * 2) + hf * 64;
#pragma unroll
        for (int q = 0; q < 4; q++) cp_async16(aw + q * 16, Ag + q * 8);
    }
}

__device__ __forceinline__ void compute_a_chunk64(char* smc, int buf, int slbuf, int tid)
{
    const float* qm  = (const float*)(smc + OFF_QM);
    const float* sL  = (const float*)(smc + OFF_SL);
    const float* slb = (const float*)(smc + OFF_SLB);
    int m = tid >> 1, kb = (tid & 1) * 32;
    float qv[8];
    *(float4*)qv       = *(const float4*)(qm + m * 8);
    *(float4*)(qv + 4) = *(const float4*)(qm + m * 8 + 4);
    unsigned outp[16];
#pragma unroll
    for (int j2 = 0; j2 < 16; j2++) {
        float v01[2];
#pragma unroll
        for (int e = 0; e < 2; e++) {
            int kl = kb + j2 * 2 + e;
            const float* lr = sL + slbuf * 512 + kl * 8;
            float v = slb[slbuf * 64 + kl];
#pragma unroll
            for (int q = 0; q < 8; q++) v += qv[q] * lr[q];
            v01[e] = fmaxf(v, 0.f);
        }
        outp[j2] = h2u(__floats2half2_rn(v01[0], v01[1]));
    }
    char* aw = smc + OFF_SA + buf * SA_BYTES + m * (GKH * 2) + kb * 2;
#pragma unroll
    for (int q4 = 0; q4 < 4; q4++)
        *(uint4*)(aw + q4 * 16) = make_uint4(outp[q4 * 4], outp[q4 * 4 + 1],
                                             outp[q4 * 4 + 2], outp[q4 * 4 + 3]);
}

template<int ASRC, int EPI>
__global__ void __launch_bounds__(256, 1)
gemm_h(const __half* __restrict__ A, const __half* __restrict__ W,
       const float* __restrict__ bias, const __half* __restrict__ resid,
       const float* __restrict__ lng, const float* __restrict__ lnbb,
       const float* __restrict__ l1w, const float* __restrict__ l1b,
       const float* __restrict__ theta,
       __half* __restrict__ C, int M, int N, int K)
{
    extern __shared__ char smc[];
    float2* sred  = (float2*)(smc + OFF_SRED);
    float*  sbias = (float*)(smc + OFF_BIAS);
    float*  sg    = (float*)(smc + OFF_G);
    float*  sbl   = (float*)(smc + OFF_BL);
    float*  qm    = (float*)(smc + OFF_QM);
    float*  sL    = (float*)(smc + OFF_SL);
    float*  slb   = (float*)(smc + OFF_SLB);

    const int tid  = threadIdx.x;
    const int lane = tid & 31;
    const int wid  = tid >> 5;
    const int bm   = blockIdx.y * 128;
    const int bn   = blockIdx.x * 256;
    const int wm   = (wid & 1) * 64;
    const int wn   = (wid >> 1) * 64;
    const int ln4  = lane >> 2;
    const int lnm  = lane & 3;
    const unsigned su = (unsigned)__cvta_generic_to_shared(smc);

    const int a_row = lane & 15;
    const int a_kq  = (lane >> 4) << 3;
    const int b_row = (lane & 7) + (((lane >> 4) & 1) << 3);
    const int b_kq  = ((lane >> 3) & 1) << 3;

    sbias[tid] = bias[bn + tid];
    if (EPI == 1) { sg[tid] = lng[tid]; sbl[tid] = lnbb[tid]; }

    if (ASRC == 1) {
        if (tid < 128) {
            const __half* hp = A + (size_t)(bm + tid) * EMB;
#pragma unroll
            for (int q = 0; q < 8; q++)
                qm[tid * 8 + q] = cosf(__half2float(hp[q])) * cosf(theta[q]);
        }
        if (tid < 128) {
            int rr = tid >> 1, hf = (tid & 1) * 4;
            *(float4*)(sL + rr * 8 + hf) = *(const float4*)(l1w + rr * 8 + hf);
        }
        if (tid < 64) slb[tid] = l1b[tid];
    }

    float acc[4][8][4];
#pragma unroll
    for (int i = 0; i < 4; i++)
#pragma unroll
        for (int j = 0; j < 8; j++)
#pragma unroll
            for (int t = 0; t < 4; t++) acc[i][j][t] = 0.f;

    const int nc = K >> 6;

    stage_chunk<ASRC>(A, W, smc, bm, bn, K, 0, 0, tid);
    cp_commit();
    if (ASRC == 1) {
        __syncthreads();
        compute_a_chunk64(smc, 0, 0, tid);
    }

    for (int c = 0; c < nc; c++) {
        const int buf = c & 1;
        const int nb  = buf ^ 1;
        if (c + 1 < nc) {
            stage_chunk<ASRC>(A, W, smc, bm, bn, K, c + 1, nb, tid);
            if (ASRC == 1) {
                if (tid < 128) {
                    int rr = tid >> 1, hf = (tid & 1) * 4;
                    *(float4*)(sL + ((c + 1) & 1) * 512 + rr * 8 + hf) =
                        *(const float4*)(l1w + ((size_t)(c + 1) * 64 + rr) * 8 + hf);
                }
                if (tid < 64) slb[((c + 1) & 1) * 64 + tid] = l1b[(c + 1) * 64 + tid];
            }
            cp_commit();
            cp_wait<1>();
        } else {
            cp_wait<0>();
        }
        __syncthreads();

        const unsigned abase = su + OFF_SA + buf * SA_BYTES;
        const unsigned bbase = su + OFF_SB + buf * SB_BYTES;

#pragma unroll
        for (int s = 0; s < 4; s++) {
            const int k0 = s * 16;
            unsigned af[4][4];
#pragma unroll
            for (int i = 0; i < 4; i++) {
                unsigned addr = abase +
                    ((wm + i * 16 + a_row) * GKH + k0 + a_kq) * 2;
                ldmx4(af[i][0], af[i][1], af[i][2], af[i][3], addr);
            }
#pragma unroll
            for (int j2 = 0; j2 < 4; j2++) {
                unsigned baddr = bbase +
                    ((wn + j2 * 16 + b_row) * GKH + k0 + b_kq) * 2;
                unsigned b0, b1, b2, b3;
                ldmx4(b0, b1, b2, b3, baddr);
#pragma unroll
                for (int i = 0; i < 4; i++) {
                    mma_f16(acc[i][2 * j2],     af[i], b0, b1);
                    mma_f16(acc[i][2 * j2 + 1], af[i], b2, b3);
                }
            }
        }

        if (ASRC == 1 && c + 1 < nc)
            compute_a_chunk64(smc, nb, (c + 1) & 1, tid);
        __syncthreads();
    }

    if (EPI == 0) {
#pragma unroll
        for (int i = 0; i < 4; i++) {
            const int gr0 = bm + wm + i * 16 + ln4;
#pragma unroll
            for (int j = 0; j < 8; j++) {
                const int col = wn + j * 8 + 2 * lnm;
                const float b0 = sbias[col], b1 = sbias[col + 1];
                *(__half2*)(C + (size_t)gr0 * N + bn + col) =
                    __floats2half2_rn(acc[i][j][0] + b0, acc[i][j][1] + b1);
                *(__half2*)(C + (size_t)(gr0 + 8) * N + bn + col) =
                    __floats2half2_rn(acc[i][j][2] + b0, acc[i][j][3] + b1);
            }
        }
    } else {
#pragma unroll
        for (int i = 0; i < 4; i++) {
            const int lr0 = wm + i * 16 + ln4;
            const int gr0 = bm + lr0;
            float s0 = 0.f, q0 = 0.f, s1 = 0.f, q1 = 0.f;
#pragma unroll
            for (int j = 0; j < 8; j++) {
                const int col = wn + j * 8 + 2 * lnm;
                const float b0 = sbias[col], b1 = sbias[col + 1];
                float2 r0 = __half22float2(*(const __half2*)(resid + (size_t)gr0 * 256 + col));
                float2 r1 = __half22float2(*(const __half2*)(resid + (size_t)(gr0 + 8) * 256 + col));
                float v0 = acc[i][j][0] + b0 + r0.x;
                float v1 = acc[i][j][1] + b1 + r0.y;
                float v2 = acc[i][j][2] + b0 + r1.x;
                float v3 = acc[i][j][3] + b1 + r1.y;
                acc[i][j][0] = v0; acc[i][j][1] = v1;
                acc[i][j][2] = v2; acc[i][j][3] = v3;
                s0 += v0 + v1; q0 += v0 * v0 + v1 * v1;
                s1 += v2 + v3; q1 += v2 * v2 + v3 * v3;
            }
#pragma unroll
            for (int o = 1; o <= 2; o <<= 1) {
                s0 += __shfl_xor_sync(0xffffffffu, s0, o);
                q0 += __shfl_xor_sync(0xffffffffu, q0, o);
                s1 += __shfl_xor_sync(0xffffffffu, s1, o);
                q1 += __shfl_xor_sync(0xffffffffu, q1, o);
            }
            if (lnm == 0) {
                sred[lr0 * 4 + (wid >> 1)]       = make_float2(s0, q0);
                sred[(lr0 + 8) * 4 + (wid >> 1)] = make_float2(s1, q1);
            }
        }
        __syncthreads();
#pragma unroll
        for (int i = 0; i < 4; i++) {
            const int lr0 = wm + i * 16 + ln4;
            const int gr0 = bm + lr0;
            float2 a0 = sred[lr0 * 4 + 0], a1 = sred[lr0 * 4 + 1];
            float2 a2 = sred[lr0 * 4 + 2], a3 = sred[lr0 * 4 + 3];
            float mean0 = (a0.x + a1.x + a2.x + a3.x) * (1.f / 256.f);
            float e0    = (a0.y + a1.y + a2.y + a3.y) * (1.f / 256.f);
            float rstd0 = rsqrtf(e0 - mean0 * mean0 + 1e-5f);
            float2 c0 = sred[(lr0 + 8) * 4 + 0], c1 = sred[(lr0 + 8) * 4 + 1];
            float2 c2 = sred[(lr0 + 8) * 4 + 2], c3 = sred[(lr0 + 8) * 4 + 3];
            float mean1 = (c0.x + c1.x + c2.x + c3.x) * (1.f / 256.f);
            float e1    = (c0.y + c1.y + c2.y + c3.y) * (1.f / 256.f);
            float rstd1 = rsqrtf(e1 - mean1 * mean1 + 1e-5f);
#pragma unroll
            for (int j = 0; j < 8; j++) {
                const int col = wn + j * 8 + 2 * lnm;
                const float g0 = sg[col], g1 = sg[col + 1];
                const float d0 = sbl[col], d1 = sbl[col + 1];
                *(__half2*)(C + (size_t)gr0 * 256 + col) = __floats2half2_rn(
                    (acc[i][j][0] - mean0) * rstd0 * g0 + d0,
                    (acc[i][j][1] - mean0) * rstd0 * g1 + d1);
                *(__half2*)(C + (size_t)(gr0 + 8) * 256 + col) = __floats2half2_rn(
                    (acc[i][j][2] - mean1) * rstd1 * g0 + d0,
                    (acc[i][j][3] - mean1) * rstd1 * g1 + d1);
            }
        }
    }
}

// ============================================================
// 4. fp16 tensor-core attention — ldmatrix fragment loads.
// ============================================================
#define KS_ST 40
#define VT_ST 216
#define PS_ST 72

__global__ void __launch_bounds__(256, 1)
attention_h(const __half* __restrict__ qkv, __half* __restrict__ o)
{
    __shared__ __half Ks[208 * KS_ST];
    __shared__ __half Vt[32 * VT_ST];
    __shared__ __half Ps[8 * 16 * PS_ST];

    const int hh = blockIdx.x;
    const int b  = blockIdx.y;
    const int tid  = threadIdx.x;
    const int lane = tid & 31;
    const int wid  = tid >> 5;
    const int r    = lane >> 2;
    const int lq   = lane & 3;
    const float scale = 0.17677669529663687f;
    const __half* base = qkv + (size_t)b * SEQ * (3 * EMB) + hh * HDIM;

    // ldmatrix lane-address components (identical mapping to gemm_h)
    const int a_row = lane & 15;
    const int a_kq  = (lane >> 4) << 3;
    const int b_row = (lane & 7) + (((lane >> 4) & 1) << 3);
    const int b_kq  = ((lane >> 3) & 1) << 3;

    for (int i = tid; i < 208 * 4; i += 256) {
        int s = i >> 2, sg = i & 3;
        float4 v = make_float4(0.f, 0.f, 0.f, 0.f);
        if (s < SEQ) v = *(const float4*)(base + (size_t)s * (3 * EMB) + EMB + sg * 8);
        *(float4*)(Ks + s * KS_ST + sg * 8) = v;
    }
    for (int i = tid; i < SEQ * 32; i += 256) {
        int s = i >> 5, d = i & 31;
        Vt[d * VT_ST + s] = base[(size_t)s * (3 * EMB) + 2 * EMB + d];
    }
    for (int i = tid; i < 32 * 20; i += 256) {
        int d = i / 20, c = SEQ + i % 20;
        Vt[d * VT_ST + c] = __float2half(0.f);
    }
    __syncthreads();

    __half* Pw = Ps + wid * 16 * PS_ST;
    const unsigned ks_su = (unsigned)__cvta_generic_to_shared(Ks);
    const unsigned vt_su = (unsigned)__cvta_generic_to_shared(Vt);
    const unsigned pw_su = (unsigned)__cvta_generic_to_shared(Pw);

    for (int strip = wid; strip < 13; strip += 8) {
        const int q0 = strip * 16 + r;
        const int q1 = q0 + 8;
        const int qa = q0 < SEQ ? q0 : SEQ - 1;
        const int qb = q1 < SEQ ? q1 : SEQ - 1;

        unsigned af[2][4];
#pragma unroll
        for (int kc = 0; kc < 2; kc++) {
            const __half* pa = base + (size_t)qa * (3 * EMB) + kc * 16 + 2 * lq;
            const __half* pc = base + (size_t)qb * (3 * EMB) + kc * 16 + 2 * lq;
            af[kc][0] = ldu(pa);
            af[kc][1] = ldu(pc);
            af[kc][2] = ldu(pa + 8);
            af[kc][3] = ldu(pc + 8);
        }

        // ---- scores: 13 key-pairs x 2 k-steps via ldmatrix.x4 ----
        float acc[26][4];
#pragma unroll
        for (int j = 0; j < 26; j++) {
            acc[j][0] = 0.f; acc[j][1] = 0.f; acc[j][2] = 0.f; acc[j][3] = 0.f;
        }
#pragma unroll
        for (int jp = 0; jp < 13; jp++) {
#pragma unroll
            for (int kc = 0; kc < 2; kc++) {
                unsigned baddr = ks_su +
                    ((jp * 16 + b_row) * KS_ST + kc * 16 + b_kq) * 2;
                unsigned b0, b1, b2, b3;
                ldmx4(b0, b1, b2, b3, baddr);
                mma_f16(acc[2 * jp],     af[kc], b0, b1);
                mma_f16(acc[2 * jp + 1], af[kc], b2, b3);
            }
        }
        if (lq >= 2) {
            acc[24][0] = -1e30f; acc[24][1] = -1e30f;
            acc[24][2] = -1e30f; acc[24][3] = -1e30f;
        }
        acc[25][0] = -1e30f; acc[25][1] = -1e30f;
        acc[25][2] = -1e30f; acc[25][3] = -1e30f;

        // ---- softmax (scale folded into exp) ----
        float m0 = -1e30f, m1 = -1e30f;
#pragma unroll
        for (int j = 0; j < 26; j++) {
            m0 = fmaxf(m0, fmaxf(acc[j][0], acc[j][1]));
            m1 = fmaxf(m1, fmaxf(acc[j][2], acc[j][3]));
        }
        m0 = fmaxf(m0, __shfl_xor_sync(0xffffffffu, m0, 1));
        m0 = fmaxf(m0, __shfl_xor_sync(0xffffffffu, m0, 2));
        m1 = fmaxf(m1, __shfl_xor_sync(0xffffffffu, m1, 1));
        m1 = fmaxf(m1, __shfl_xor_sync(0xffffffffu, m1, 2));
        float l0 = 0.f, l1 = 0.f;
#pragma unroll
        for (int j = 0; j < 26; j++) {
            acc[j][0] = __expf((acc[j][0] - m0) * scale);
            acc[j][1] = __expf((acc[j][1] - m0) * scale);
            acc[j][2] = __expf((acc[j][2] - m1) * scale);
            acc[j][3] = __expf((acc[j][3] - m1) * scale);
            l0 += acc[j][0] + acc[j][1];
            l1 += acc[j][2] + acc[j][3];
        }
        l0 += __shfl_xor_sync(0xffffffffu, l0, 1);
        l0 += __shfl_xor_sync(0xffffffffu, l0, 2);
        l1 += __shfl_xor_sync(0xffffffffu, l1, 1);
        l1 += __shfl_xor_sync(0xffffffffu, l1, 2);
        const float inv0 = 1.f / l0;
        const float inv1 = 1.f / l1;

        // ---- P @ V in chunks of 64 keys, ldmatrix loads ----
        float O[4][4];
#pragma unroll
        for (int nt = 0; nt < 4; nt++) {
            O[nt][0] = 0.f; O[nt][1] = 0.f; O[nt][2] = 0.f; O[nt][3] = 0.f;
        }
#pragma unroll
        for (int ch = 0; ch < 4; ch++) {
            const int njt = (ch < 3) ? 8 : 2;
#pragma unroll
            for (int jj = 0; jj < 8; jj++) {
                if (jj < njt) {
                    const int j = ch * 8 + jj;
                    *(__half2*)(Pw + r * PS_ST + jj * 8 + 2 * lq) =
                        __floats2half2_rn(acc[j][0], acc[j][1]);
                    *(__half2*)(Pw + (r + 8) * PS_ST + jj * 8 + 2 * lq) =
                        __floats2half2_rn(acc[j][2], acc[j][3]);
                }
            }
            __syncwarp();
            const int nkk = (ch < 3) ? 4 : 1;
#pragma unroll
            for (int kk = 0; kk < 4; kk++) {
                if (kk < nkk) {
                    unsigned pa[4];
                    unsigned paddr = pw_su + (a_row * PS_ST + kk * 16 + a_kq) * 2;
                    ldmx4(pa[0], pa[1], pa[2], pa[3], paddr);
#pragma unroll
                    for (int ntp = 0; ntp < 2; ntp++) {
                        unsigned vaddr = vt_su +
                            ((ntp * 16 + b_row) * VT_ST + ch * 64 + kk * 16 + b_kq) * 2;
                        unsigned b0, b1, b2, b3;
                        ldmx4(b0, b1, b2, b3, vaddr);
                        mma_f16(O[2 * ntp],     pa, b0, b1);
                        mma_f16(O[2 * ntp + 1], pa, b2, b3);
                    }
                }
            }
            __syncwarp();
        }

        if (q0 < SEQ) {
            __half* op = o + (size_t)(b * SEQ + q0) * EMB + hh * HDIM + 2 * lq;
#pragma unroll
            for (int nt = 0; nt < 4; nt++)
                *(__half2*)(op + nt * 8) =
                    __floats2half2_rn(O[nt][0] * inv0, O[nt][1] * inv0);
        }
        if (q1 < SEQ) {
            __half* op = o + (size_t)(b * SEQ + q1) * EMB + hh * HDIM + 2 * lq;
#pragma unroll
            for (int nt = 0; nt < 4; nt++)
                *(__half2*)(op + nt * 8) =
                    __floats2half2_rn(O[nt][2] * inv1, O[nt][3] * inv1);
        }
    }
}

// ============================================================
// 7. Mean-pool + classifier (h is fp16)
// ============================================================
__global__ void __launch_bounds__(256)
pool_cls_kernel(const __half* __restrict__ h, const float* __restrict__ cw,
                const float* __restrict__ cb, float* __restrict__ out)
{
    int b = blockIdx.x;
    int e = threadIdx.x;
    const __half* hp = h + (size_t)b * SEQ * EMB + e;
    float s = 0.f;
    for (int t = 0; t < SEQ; t++) s += __half2float(hp[(size_t)t * EMB]);
    __shared__ float sp[EMB];
    sp[e] = s * (1.f / 196.f);
    __syncthreads();
    if (e < NCLS) {
        float acc = cb[e];
        const float* w = cw + e * EMB;
        for (int k = 0; k < EMB; k++) acc += sp[k] * w[k];
        out[b * NCLS + e] = acc;
    }
}

// ============================================================
// launcher
// ============================================================
extern "C" void kernel_launch(void* const* d_in, const int* in_sizes, int n_in,
                              void* d_out, int out_size)
{
    const float* x    = (const float*)d_in[0];
    const float* qfw  = (const float*)d_in[1];
    const float* qfb  = (const float*)d_in[2];
    const float* pww  = (const float*)d_in[3];
    const float* pwb  = (const float*)d_in[4];
    const float* embw = (const float*)d_in[5];
    const float* embb = (const float*)d_in[6];
    const float* inw  = (const float*)d_in[7];
    const float* inb  = (const float*)d_in[8];
    const float* outw = (const float*)d_in[9];
    const float* outb = (const float*)d_in[10];
    const float* thet = (const float*)d_in[11];
    const float* l1w  = (const float*)d_in[12];
    const float* l1b  = (const float*)d_in[13];
    const float* l2w  = (const float*)d_in[14];
    const float* l2b  = (const float*)d_in[15];
    const float* ln1g = (const float*)d_in[16];
    const float* ln1b = (const float*)d_in[17];
    const float* ln2g = (const float*)d_in[18];
    const float* ln2b = (const float*)d_in[19];
    const float* clsw = (const float*)d_in[20];
    const float* clsb = (const float*)d_in[21];
    float* out = (float*)d_out;

    __half *h, *qkv, *attn, *w_in, *w_out, *w_l2;
    float *feat, *pe;
    cudaGetSymbolAddress((void**)&h,     g_h);
    cudaGetSymbolAddress((void**)&qkv,   g_qkv);
    cudaGetSymbolAddress((void**)&attn,  g_attn);
    cudaGetSymbolAddress((void**)&feat,  g_feat);
    cudaGetSymbolAddress((void**)&pe,    g_pe);
    cudaGetSymbolAddress((void**)&w_in,  g_w_in);
    cudaGetSymbolAddress((void**)&w_out, g_w_out);
    cudaGetSymbolAddress((void**)&w_l2,  g_w_l2);

    cudaFuncSetAttribute(gemm_h<0,0>,
                         cudaFuncAttributeMaxDynamicSharedMemorySize, SMEM_GH);
    cudaFuncSetAttribute(gemm_h<0,1>,
                         cudaFuncAttributeMaxDynamicSharedMemorySize, SMEM_GH);
    cudaFuncSetAttribute(gemm_h<1,1>,
                         cudaFuncAttributeMaxDynamicSharedMemorySize, SMEM_GH);

    const int n_in_w  = NBLK * 3 * EMB * EMB;
    const int n_out_w = NBLK * EMB * EMB;
    const int n_l2_w  = NBLK * EMB * FF;
    h_cvt_kernel<<<(n_in_w  + 255) / 256, 256>>>(inw,  w_in,  n_in_w);
    h_cvt_kernel<<<(n_out_w + 255) / 256, 256>>>(outw, w_out, n_out_w);
    h_cvt_kernel<<<(n_l2_w  + 255) / 256, 256>>>(l2w,  w_l2,  n_l2_w);
    pe_kernel<<<SEQ, EMB>>>(pe);

    quanv_kernel<<<(TOK * 4 + 255) / 256, 256>>>(x, qfw, qfb, pww, pwb, feat);
    embed_kernel<<<TOK, 256>>>(feat, embw, embb, pe, h);

    for (int i = 0; i < NBLK; i++) {
        gemm_h<0,0><<<dim3(3, TOK / 128), 256, SMEM_GH>>>(
            h, w_in + (size_t)i * 3 * EMB * EMB, inb + (size_t)i * 3 * EMB,
            nullptr, nullptr, nullptr, nullptr, nullptr, nullptr,
            qkv, TOK, 3 * EMB, EMB);

        attention_h<<<dim3(HEADS, BATCH), 256>>>(qkv, attn);

        gemm_h<0,1><<<dim3(1, TOK / 128), 256, SMEM_GH>>>(
            attn, w_out + (size_t)i * EMB * EMB, outb + (size_t)i * EMB,
            h, ln1g + (size_t)i * EMB, ln1b + (size_t)i * EMB,
            nullptr, nullptr, nullptr,
            h, TOK, EMB, EMB);

        gemm_h<1,1><<<dim3(1, TOK / 128), 256, SMEM_GH>>>(
            h, w_l2 + (size_t)i * EMB * FF, l2b + (size_t)i * EMB,
            h, ln2g + (size_t)i * EMB, ln2b + (size_t)i * EMB,
            l1w + (size_t)i * FF * NQBIT, l1b + (size_t)i * FF,
            thet + (size_t)i * NQBIT,
            h, TOK, EMB, FF);
    }

    pool_cls_kernel<<<BATCH, 256>>>(h, clsw, clsb, out);
}